// round 4
// baseline (speedup 1.0000x reference)
#include <cuda_runtime.h>
#include <cuda_bf16.h>
#include <cstdint>
#include <math.h>

#define NE      800000
#define NNODE   50000
#define TILE    128
#define NT      (NE / TILE)     // 6250
#define THREADS 512             // 16 warps, grid 4(M)x4(N)

// ---------------- edge kernel SMEM ----------------
#define XSTRIDE 336             // 168 bf16 cols (160 + pad), 21*16B -> conflict-free
#define WSTRIDE 336
#define E_XH    0
#define E_XL    (E_XH + 128 * XSTRIDE)      // 43008
#define E_WH    (E_XL + 128 * XSTRIDE)      // 86016
#define E_WL    (E_WH + 160 * WSTRIDE)      // 139776
#define E_BIAS  (E_WL + 160 * WSTRIDE)      // 193536
#define E_SMEM  (E_BIAS + 640)              // 194176

// ---------------- gate kernel SMEM ----------------
#define MSTRIDE 272             // 136 bf16 cols, 17*16B -> conflict-free
#define G_MH    0
#define G_ML    (G_MH + 128 * MSTRIDE)      // 34816
#define G_WH    (G_ML + 128 * MSTRIDE)      // 69632
#define G_WL    (G_WH + 128 * MSTRIDE)      // 104448
#define G_LSIG  (G_WL + 128 * MSTRIDE)      // 139264
#define G_LSP   (G_LSIG + 1024 * 8)         // 147456
#define G_BF    (G_LSP + 1024 * 8)          // 155648
#define G_BS    (G_BF + 256)
#define G_SMEM  (G_BS + 256)                // 156160

static __device__ __forceinline__ uint32_t smem_u32(const void* p) {
    uint32_t a;
    asm("{ .reg .u64 t; cvta.to.shared.u64 t, %1; cvt.u32.u64 %0, t; }" : "=r"(a) : "l"(p));
    return a;
}
static __device__ __forceinline__ void ldm_x4(uint32_t* r, uint32_t addr) {
    asm volatile("ldmatrix.sync.aligned.m8n8.x4.shared.b16 {%0,%1,%2,%3}, [%4];"
                 : "=r"(r[0]), "=r"(r[1]), "=r"(r[2]), "=r"(r[3]) : "r"(addr));
}
static __device__ __forceinline__ void ldm_x2t(uint32_t* r, uint32_t addr) {
    asm volatile("ldmatrix.sync.aligned.m8n8.x2.trans.shared.b16 {%0,%1}, [%2];"
                 : "=r"(r[0]), "=r"(r[1]) : "r"(addr));
}
static __device__ __forceinline__ void mma_bf16(float* c, const uint32_t* a, const uint32_t* b) {
    asm volatile("mma.sync.aligned.m16n8k16.row.col.f32.bf16.bf16.f32 "
                 "{%0,%1,%2,%3}, {%4,%5,%6,%7}, {%8,%9}, {%0,%1,%2,%3};"
                 : "+f"(c[0]), "+f"(c[1]), "+f"(c[2]), "+f"(c[3])
                 : "r"(a[0]), "r"(a[1]), "r"(a[2]), "r"(a[3]), "r"(b[0]), "r"(b[1]));
}
static __device__ __forceinline__ void split2(float x0, float x1, uint32_t& hi, uint32_t& lo) {
    uint32_t h;
    asm("cvt.rn.bf16x2.f32 %0, %1, %2;" : "=r"(h) : "f"(x1), "f"(x0)); // first src -> upper half
    float h0 = __uint_as_float(h << 16);
    float h1 = __uint_as_float(h & 0xFFFF0000u);
    uint32_t l;
    asm("cvt.rn.bf16x2.f32 %0, %1, %2;" : "=r"(l) : "f"(x1 - h1), "f"(x0 - h0));
    hi = h; lo = l;
}

// =====================================================================
// Kernel 1: z_edge = relu(cat(z_src, z_dst, ea) @ Wffw + b), 3-product bf16
// =====================================================================
__global__ __launch_bounds__(THREADS, 1)
void edge_mlp_kernel(const float* __restrict__ z,
                     const float* __restrict__ ea,
                     const int*   __restrict__ srcp,
                     const int*   __restrict__ dstp,
                     const float* __restrict__ W,
                     const float* __restrict__ bias,
                     float* __restrict__ z_edge)
{
    extern __shared__ char sm[];
    const uint32_t sb = smem_u32(sm);
    const int tid = threadIdx.x, wid = tid >> 5, lane = tid & 31;
    const int mi = wid >> 2, ni = wid & 3;          // rows mi*32, cols ni*40

    for (int idx = tid; idx < 160 * 160; idx += THREADS) {
        const int k = idx / 160, n = idx - k * 160;
        const float w = W[idx];
        const __nv_bfloat16 h = __float2bfloat16(w);
        const __nv_bfloat16 l = __float2bfloat16(w - __bfloat162float(h));
        *reinterpret_cast<__nv_bfloat16*>(sm + E_WH + k * WSTRIDE + n * 2) = h;
        *reinterpret_cast<__nv_bfloat16*>(sm + E_WL + k * WSTRIDE + n * 2) = l;
    }
    if (tid < 160) reinterpret_cast<float*>(sm + E_BIAS)[tid] = bias[tid];

    const int e_loc = tid >> 2, q = tid & 3;        // 4 threads per edge row
    const float* s_bias = reinterpret_cast<const float*>(sm + E_BIAS);

    for (int t = blockIdx.x; t < NT; t += gridDim.x) {
        __syncthreads();   // previous tile fully consumed (covers weight init too)

        // ---- gather: thread covers x cols [q*40, q*40+40) of its edge ----
        {
            const int ge = t * TILE + e_loc;
            float4 v[10];
            if (q == 0) {
                const float4* zs = reinterpret_cast<const float4*>(z + (size_t)srcp[ge] * 64);
                #pragma unroll
                for (int i = 0; i < 10; i++) v[i] = zs[i];
            } else if (q == 1) {
                const float4* zs = reinterpret_cast<const float4*>(z + (size_t)srcp[ge] * 64);
                const float4* zd = reinterpret_cast<const float4*>(z + (size_t)dstp[ge] * 64);
                #pragma unroll
                for (int i = 0; i < 6; i++) v[i] = zs[10 + i];
                #pragma unroll
                for (int i = 0; i < 4; i++) v[6 + i] = zd[i];
            } else if (q == 2) {
                const float4* zd = reinterpret_cast<const float4*>(z + (size_t)dstp[ge] * 64);
                #pragma unroll
                for (int i = 0; i < 10; i++) v[i] = zd[4 + i];
            } else {
                const float4* zd = reinterpret_cast<const float4*>(z + (size_t)dstp[ge] * 64);
                const float4* ep = reinterpret_cast<const float4*>(ea + (size_t)ge * 32);
                v[0] = zd[14]; v[1] = zd[15];
                #pragma unroll
                for (int i = 0; i < 8; i++) v[2 + i] = ep[i];
            }
            uint32_t* xh = reinterpret_cast<uint32_t*>(sm + E_XH + e_loc * XSTRIDE) + q * 20;
            uint32_t* xl = reinterpret_cast<uint32_t*>(sm + E_XL + e_loc * XSTRIDE) + q * 20;
            #pragma unroll
            for (int i = 0; i < 10; i++) {
                uint32_t h0, l0, h1, l1;
                split2(v[i].x, v[i].y, h0, l0);
                split2(v[i].z, v[i].w, h1, l1);
                xh[2 * i] = h0; xh[2 * i + 1] = h1;
                xl[2 * i] = l0; xl[2 * i + 1] = l1;
            }
        }
        __syncthreads();

        // ---- GEMM: rows mi*32..+31 (2 m-tiles), cols ni*40..+39 (5 n-tiles) ----
        float acc[2][5][4];
        #pragma unroll
        for (int m = 0; m < 2; m++)
            #pragma unroll
            for (int n = 0; n < 5; n++)
                #pragma unroll
                for (int r = 0; r < 4; r++) acc[m][n][r] = 0.0f;

        #pragma unroll 2
        for (int k = 0; k < 10; k++) {
            uint32_t ah[2][4], al[2][4];
            const uint32_t arow = (uint32_t)(mi * 32 + (lane & 15)) * XSTRIDE
                                + (uint32_t)k * 32 + ((lane >> 4) << 4);
            #pragma unroll
            for (int m = 0; m < 2; m++) {
                ldm_x4(ah[m], sb + E_XH + arow + m * 16 * XSTRIDE);
                ldm_x4(al[m], sb + E_XL + arow + m * 16 * XSTRIDE);
            }
            const uint32_t brow = (uint32_t)(k * 16 + (lane & 15)) * WSTRIDE + (uint32_t)ni * 80;
            #pragma unroll
            for (int n = 0; n < 5; n++) {
                uint32_t bh[2], bl[2];
                ldm_x2t(bh, sb + E_WH + brow + n * 16);
                ldm_x2t(bl, sb + E_WL + brow + n * 16);
                #pragma unroll
                for (int m = 0; m < 2; m++) {
                    mma_bf16(acc[m][n], ah[m], bh);
                    mma_bf16(acc[m][n], al[m], bh);
                    mma_bf16(acc[m][n], ah[m], bl);
                }
            }
        }

        // ---- epilogue: bias + relu ----
        const int r0 = t * TILE + mi * 32 + (lane >> 2);
        #pragma unroll
        for (int n = 0; n < 5; n++) {
            const int col = ni * 40 + n * 8 + 2 * (lane & 3);
            const float b0 = s_bias[col], b1 = s_bias[col + 1];
            #pragma unroll
            for (int m = 0; m < 2; m++) {
                float2 o0, o1;
                o0.x = fmaxf(acc[m][n][0] + b0, 0.0f);
                o0.y = fmaxf(acc[m][n][1] + b1, 0.0f);
                o1.x = fmaxf(acc[m][n][2] + b0, 0.0f);
                o1.y = fmaxf(acc[m][n][3] + b1, 0.0f);
                *reinterpret_cast<float2*>(z_edge + (size_t)(r0 + m * 16) * 160 + col) = o0;
                *reinterpret_cast<float2*>(z_edge + (size_t)(r0 + m * 16 + 8) * 160 + col) = o1;
            }
        }
    }
}

// =====================================================================
// Kernel 2: gate branch, 3-product bf16, paired f/s per warp, in-register
//           epilogue, 1024-entry LUTs, float2 scatter atomics
// =====================================================================
static __device__ __forceinline__ float lut_eval(const float2* tab, float x) {
    float tp = fmaf(x, 1024.0f / 24.0f, 512.0f);   // [-12,12] -> [0,1024)
    tp = fminf(fmaxf(tp, 0.0f), 1023.0f);
    const int i = (int)tp;
    const float fr = tp - (float)i;
    const float2 c = tab[i];
    return fmaf(fr, c.y, c.x);
}

__global__ __launch_bounds__(THREADS, 1)
void gate_kernel(const float* __restrict__ z,
                 const int*   __restrict__ srcp,
                 const int*   __restrict__ dstp,
                 const float* __restrict__ Wf,
                 const float* __restrict__ bf,
                 const float* __restrict__ Ws,
                 const float* __restrict__ bs,
                 float* __restrict__ z_node)
{
    extern __shared__ char sm[];
    const uint32_t sb = smem_u32(sm);
    const int tid = threadIdx.x, wid = tid >> 5, lane = tid & 31;
    const int mi = wid >> 2, ni = wid & 3;   // rows mi*32; f cols ni*16, s cols 64+ni*16

    // combined W [K=128][N=128]: n<64 -> Wf col n, else Ws col n-64 (hi/lo)
    for (int idx = tid; idx < 128 * 128; idx += THREADS) {
        const int k = idx >> 7, n = idx & 127;
        const float w = (n < 64) ? Wf[k * 64 + n] : Ws[k * 64 + (n - 64)];
        const __nv_bfloat16 h = __float2bfloat16(w);
        const __nv_bfloat16 l = __float2bfloat16(w - __bfloat162float(h));
        *reinterpret_cast<__nv_bfloat16*>(sm + G_WH + k * MSTRIDE + n * 2) = h;
        *reinterpret_cast<__nv_bfloat16*>(sm + G_WL + k * MSTRIDE + n * 2) = l;
    }
    for (int i = tid; i < 1024; i += THREADS) {
        const float x0 = -12.0f + (float)i * (24.0f / 1024.0f);
        const float x1 = x0 + (24.0f / 1024.0f);
        const float s0 = 1.0f / (1.0f + expf(-x0));
        const float s1 = 1.0f / (1.0f + expf(-x1));
        reinterpret_cast<float2*>(sm + G_LSIG)[i] = make_float2(s0, s1 - s0);
        const float p0 = fmaxf(x0, 0.0f) + log1pf(expf(-fabsf(x0)));
        const float p1 = fmaxf(x1, 0.0f) + log1pf(expf(-fabsf(x1)));
        reinterpret_cast<float2*>(sm + G_LSP)[i] = make_float2(p0, p1 - p0);
    }
    if (tid < 64) {
        reinterpret_cast<float*>(sm + G_BF)[tid] = bf[tid];
        reinterpret_cast<float*>(sm + G_BS)[tid] = bs[tid];
    }

    const float2* t_sig = reinterpret_cast<const float2*>(sm + G_LSIG);
    const float2* t_sp  = reinterpret_cast<const float2*>(sm + G_LSP);
    const float*  s_bf  = reinterpret_cast<const float*>(sm + G_BF);
    const float*  s_bs  = reinterpret_cast<const float*>(sm + G_BS);
    const int e_loc = tid >> 2, q = tid & 3;   // 4 threads/edge, 32 m-cols each

    for (int t = blockIdx.x; t < NT; t += gridDim.x) {
        __syncthreads();

        // ---- gather m = cat(z_dst, z_src): q0,q1 -> dst cols 0-63; q2,q3 -> src 64-127 ----
        {
            const int ge = t * TILE + e_loc;
            const int node = (q < 2) ? dstp[ge] : srcp[ge];
            const float4* zr = reinterpret_cast<const float4*>(z + (size_t)node * 64) + (q & 1) * 8;
            uint32_t* mh = reinterpret_cast<uint32_t*>(sm + G_MH + e_loc * MSTRIDE) + q * 16;
            uint32_t* ml = reinterpret_cast<uint32_t*>(sm + G_ML + e_loc * MSTRIDE) + q * 16;
            #pragma unroll
            for (int i = 0; i < 8; i++) {
                const float4 v = zr[i];
                uint32_t h0, l0, h1, l1;
                split2(v.x, v.y, h0, l0);
                split2(v.z, v.w, h1, l1);
                mh[2 * i] = h0; mh[2 * i + 1] = h1;
                ml[2 * i] = l0; ml[2 * i + 1] = l1;
            }
        }
        __syncthreads();

        // ---- GEMM: accf (cols ni*16..+15), accs (cols 64+ni*16..+15) ----
        float accf[2][2][4], accs[2][2][4];
        #pragma unroll
        for (int m = 0; m < 2; m++)
            #pragma unroll
            for (int n = 0; n < 2; n++)
                #pragma unroll
                for (int r = 0; r < 4; r++) { accf[m][n][r] = 0.0f; accs[m][n][r] = 0.0f; }

        #pragma unroll 2
        for (int k = 0; k < 8; k++) {
            uint32_t ah[2][4], al[2][4];
            const uint32_t arow = (uint32_t)(mi * 32 + (lane & 15)) * MSTRIDE
                                + (uint32_t)k * 32 + ((lane >> 4) << 4);
            #pragma unroll
            for (int m = 0; m < 2; m++) {
                ldm_x4(ah[m], sb + G_MH + arow + m * 16 * MSTRIDE);
                ldm_x4(al[m], sb + G_ML + arow + m * 16 * MSTRIDE);
            }
            const uint32_t brow = (uint32_t)(k * 16 + (lane & 15)) * MSTRIDE;
            #pragma unroll
            for (int n = 0; n < 2; n++) {
                uint32_t bfh[2], bfl[2], bsh[2], bsl[2];
                const uint32_t fcol = (uint32_t)(ni * 32 + n * 16);
                ldm_x2t(bfh, sb + G_WH + brow + fcol);
                ldm_x2t(bfl, sb + G_WL + brow + fcol);
                ldm_x2t(bsh, sb + G_WH + brow + 128 + fcol);
                ldm_x2t(bsl, sb + G_WL + brow + 128 + fcol);
                #pragma unroll
                for (int m = 0; m < 2; m++) {
                    mma_bf16(accf[m][n], ah[m], bfh);
                    mma_bf16(accf[m][n], al[m], bfh);
                    mma_bf16(accf[m][n], ah[m], bfl);
                    mma_bf16(accs[m][n], ah[m], bsh);
                    mma_bf16(accs[m][n], al[m], bsh);
                    mma_bf16(accs[m][n], ah[m], bsl);
                }
            }
        }

        // ---- in-register gate + scatter (float2 atomics) ----
        #pragma unroll
        for (int m = 0; m < 2; m++) {
            const int ra = t * TILE + mi * 32 + m * 16 + (lane >> 2);
            const int da = dstp[ra];
            const int db = dstp[ra + 8];
            #pragma unroll
            for (int n = 0; n < 2; n++) {
                const int c = ni * 16 + n * 8 + 2 * (lane & 3);
                const float bf0 = s_bf[c], bf1 = s_bf[c + 1];
                const float bs0 = s_bs[c], bs1 = s_bs[c + 1];
                float2 m0, m1;
                m0.x = lut_eval(t_sig, accf[m][n][0] + bf0) *
                       fmaxf(lut_eval(t_sp, accs[m][n][0] + bs0), accs[m][n][0] + bs0);
                m0.y = lut_eval(t_sig, accf[m][n][1] + bf1) *
                       fmaxf(lut_eval(t_sp, accs[m][n][1] + bs1), accs[m][n][1] + bs1);
                m1.x = lut_eval(t_sig, accf[m][n][2] + bf0) *
                       fmaxf(lut_eval(t_sp, accs[m][n][2] + bs0), accs[m][n][2] + bs0);
                m1.y = lut_eval(t_sig, accf[m][n][3] + bf1) *
                       fmaxf(lut_eval(t_sp, accs[m][n][3] + bs1), accs[m][n][3] + bs1);
                atomicAdd(reinterpret_cast<float2*>(z_node + (size_t)da * 64 + c), m0);
                atomicAdd(reinterpret_cast<float2*>(z_node + (size_t)db * 64 + c), m1);
            }
        }
    }
}

extern "C" void kernel_launch(void* const* d_in, const int* in_sizes, int n_in,
                              void* d_out, int out_size)
{
    const float* z    = (const float*)d_in[0];
    const float* ea   = (const float*)d_in[1];
    const int*   eidx = (const int*)  d_in[2];
    const float* Wffw = (const float*)d_in[3];
    const float* bffw = (const float*)d_in[4];
    const float* Wf   = (const float*)d_in[5];
    const float* bf   = (const float*)d_in[6];
    const float* Ws   = (const float*)d_in[7];
    const float* bs   = (const float*)d_in[8];

    float* z_node = (float*)d_out;
    float* z_edge = (float*)d_out + (size_t)NNODE * 64;
    const int* srcp = eidx;
    const int* dstp = eidx + NE;

    cudaMemcpyAsync(z_node, z, (size_t)NNODE * 64 * sizeof(float),
                    cudaMemcpyDeviceToDevice, 0);

    cudaFuncSetAttribute(edge_mlp_kernel, cudaFuncAttributeMaxDynamicSharedMemorySize, E_SMEM);
    cudaFuncSetAttribute(gate_kernel,     cudaFuncAttributeMaxDynamicSharedMemorySize, G_SMEM);

    edge_mlp_kernel<<<148, THREADS, E_SMEM, 0>>>(z, ea, srcp, dstp, Wffw, bffw, z_edge);
    gate_kernel<<<148, THREADS, G_SMEM, 0>>>(z, srcp, dstp, Wf, bf, Ws, bs, z_node);
}

// round 5
// speedup vs baseline: 1.0532x; 1.0532x over previous
#include <cuda_runtime.h>
#include <cuda_bf16.h>
#include <cstdint>
#include <math.h>

#define NE      800000
#define NNODE   50000

// ---------------- edge kernel ----------------
#define TILE1   128
#define NT1     (NE / TILE1)            // 6250
#define THR1    512
#define XSTRIDE 336
#define WSTRIDE 336
#define E_XH    0
#define E_XL    (E_XH + 128 * XSTRIDE)
#define E_WH    (E_XL + 128 * XSTRIDE)
#define E_WL    (E_WH + 160 * WSTRIDE)
#define E_BIAS  (E_WL + 160 * WSTRIDE)
#define E_SMEM  (E_BIAS + 640)          // 194176

// ---------------- gate kernel ----------------
#define TILE2   64
#define NT2     (NE / TILE2)            // 12500
#define THR2    256
#define MSTRIDE 272
#define G_MH    0
#define G_ML    (G_MH + TILE2 * MSTRIDE)    // 17408
#define G_WH    (G_ML + TILE2 * MSTRIDE)    // 34816
#define G_WL    (G_WH + 128 * MSTRIDE)      // 69632
#define G_LSIG  (G_WL + 128 * MSTRIDE)      // 104448
#define G_LSP   (G_LSIG + 512 * 8)          // 108544
#define G_BF    (G_LSP + 512 * 8)           // 112640
#define G_BS    (G_BF + 256)
#define G_SMEM  (G_BS + 256)                // 113152  (2 CTAs/SM)

static __device__ __forceinline__ uint32_t smem_u32(const void* p) {
    uint32_t a;
    asm("{ .reg .u64 t; cvta.to.shared.u64 t, %1; cvt.u32.u64 %0, t; }" : "=r"(a) : "l"(p));
    return a;
}
static __device__ __forceinline__ void ldm_x4(uint32_t* r, uint32_t addr) {
    asm volatile("ldmatrix.sync.aligned.m8n8.x4.shared.b16 {%0,%1,%2,%3}, [%4];"
                 : "=r"(r[0]), "=r"(r[1]), "=r"(r[2]), "=r"(r[3]) : "r"(addr));
}
static __device__ __forceinline__ void ldm_x2t(uint32_t* r, uint32_t addr) {
    asm volatile("ldmatrix.sync.aligned.m8n8.x2.trans.shared.b16 {%0,%1}, [%2];"
                 : "=r"(r[0]), "=r"(r[1]) : "r"(addr));
}
static __device__ __forceinline__ void mma_bf16(float* c, const uint32_t* a, const uint32_t* b) {
    asm volatile("mma.sync.aligned.m16n8k16.row.col.f32.bf16.bf16.f32 "
                 "{%0,%1,%2,%3}, {%4,%5,%6,%7}, {%8,%9}, {%0,%1,%2,%3};"
                 : "+f"(c[0]), "+f"(c[1]), "+f"(c[2]), "+f"(c[3])
                 : "r"(a[0]), "r"(a[1]), "r"(a[2]), "r"(a[3]), "r"(b[0]), "r"(b[1]));
}
static __device__ __forceinline__ void split2(float x0, float x1, uint32_t& hi, uint32_t& lo) {
    uint32_t h;
    asm("cvt.rn.bf16x2.f32 %0, %1, %2;" : "=r"(h) : "f"(x1), "f"(x0));
    float h0 = __uint_as_float(h << 16);
    float h1 = __uint_as_float(h & 0xFFFF0000u);
    uint32_t l;
    asm("cvt.rn.bf16x2.f32 %0, %1, %2;" : "=r"(l) : "f"(x1 - h1), "f"(x0 - h0));
    hi = h; lo = l;
}

// =====================================================================
// Kernel 1: z_edge = relu(cat(z_src, z_dst, ea) @ Wffw + b), 3-product bf16
// =====================================================================
static __device__ __forceinline__ void edge_preload(float4* v, int ge, int q,
                                                    const float* __restrict__ z,
                                                    const float* __restrict__ ea,
                                                    const int* __restrict__ srcp,
                                                    const int* __restrict__ dstp)
{
    if (q == 0) {
        const float4* zs = reinterpret_cast<const float4*>(z + (size_t)srcp[ge] * 64);
        #pragma unroll
        for (int i = 0; i < 10; i++) v[i] = zs[i];
    } else if (q == 1) {
        const float4* zs = reinterpret_cast<const float4*>(z + (size_t)srcp[ge] * 64);
        const float4* zd = reinterpret_cast<const float4*>(z + (size_t)dstp[ge] * 64);
        #pragma unroll
        for (int i = 0; i < 6; i++) v[i] = zs[10 + i];
        #pragma unroll
        for (int i = 0; i < 4; i++) v[6 + i] = zd[i];
    } else if (q == 2) {
        const float4* zd = reinterpret_cast<const float4*>(z + (size_t)dstp[ge] * 64);
        #pragma unroll
        for (int i = 0; i < 10; i++) v[i] = zd[4 + i];
    } else {
        const float4* zd = reinterpret_cast<const float4*>(z + (size_t)dstp[ge] * 64);
        const float4* ep = reinterpret_cast<const float4*>(ea + (size_t)ge * 32);
        v[0] = zd[14]; v[1] = zd[15];
        #pragma unroll
        for (int i = 0; i < 8; i++) v[2 + i] = ep[i];
    }
}

__global__ __launch_bounds__(THR1, 1)
void edge_mlp_kernel(const float* __restrict__ z,
                     const float* __restrict__ ea,
                     const int*   __restrict__ srcp,
                     const int*   __restrict__ dstp,
                     const float* __restrict__ W,
                     const float* __restrict__ bias,
                     float* __restrict__ z_edge)
{
    extern __shared__ char sm[];
    const uint32_t sb = smem_u32(sm);
    const int tid = threadIdx.x, wid = tid >> 5, lane = tid & 31;
    const int mi = wid >> 2, ni = wid & 3;

    for (int idx = tid; idx < 160 * 160; idx += THR1) {
        const int k = idx / 160, n = idx - k * 160;
        const float w = W[idx];
        const __nv_bfloat16 h = __float2bfloat16(w);
        const __nv_bfloat16 l = __float2bfloat16(w - __bfloat162float(h));
        *reinterpret_cast<__nv_bfloat16*>(sm + E_WH + k * WSTRIDE + n * 2) = h;
        *reinterpret_cast<__nv_bfloat16*>(sm + E_WL + k * WSTRIDE + n * 2) = l;
    }
    if (tid < 160) reinterpret_cast<float*>(sm + E_BIAS)[tid] = bias[tid];

    const int e_loc = tid >> 2, q = tid & 3;
    const float* s_bias = reinterpret_cast<const float*>(sm + E_BIAS);

    float4 v[10];
    int t = blockIdx.x;
    if (t < NT1) edge_preload(v, t * TILE1 + e_loc, q, z, ea, srcp, dstp);

    for (; t < NT1; t += gridDim.x) {
        __syncthreads();   // previous tile fully consumed (covers weight init too)

        // ---- STS from prefetched registers ----
        {
            uint32_t* xh = reinterpret_cast<uint32_t*>(sm + E_XH + e_loc * XSTRIDE) + q * 20;
            uint32_t* xl = reinterpret_cast<uint32_t*>(sm + E_XL + e_loc * XSTRIDE) + q * 20;
            #pragma unroll
            for (int i = 0; i < 10; i++) {
                uint32_t h0, l0, h1, l1;
                split2(v[i].x, v[i].y, h0, l0);
                split2(v[i].z, v[i].w, h1, l1);
                xh[2 * i] = h0; xh[2 * i + 1] = h1;
                xl[2 * i] = l0; xl[2 * i + 1] = l1;
            }
        }
        __syncthreads();

        // ---- prefetch next tile during GEMM ----
        const int tn = t + gridDim.x;
        if (tn < NT1) edge_preload(v, tn * TILE1 + e_loc, q, z, ea, srcp, dstp);

        // ---- GEMM: rows mi*32..+31, cols ni*40..+39 ----
        float acc[2][5][4];
        #pragma unroll
        for (int m = 0; m < 2; m++)
            #pragma unroll
            for (int n = 0; n < 5; n++)
                #pragma unroll
                for (int r = 0; r < 4; r++) acc[m][n][r] = 0.0f;

        #pragma unroll 2
        for (int k = 0; k < 10; k++) {
            uint32_t ah[2][4], al[2][4];
            const uint32_t arow = (uint32_t)(mi * 32 + (lane & 15)) * XSTRIDE
                                + (uint32_t)k * 32 + ((lane >> 4) << 4);
            #pragma unroll
            for (int m = 0; m < 2; m++) {
                ldm_x4(ah[m], sb + E_XH + arow + m * 16 * XSTRIDE);
                ldm_x4(al[m], sb + E_XL + arow + m * 16 * XSTRIDE);
            }
            const uint32_t brow = (uint32_t)(k * 16 + (lane & 15)) * WSTRIDE + (uint32_t)ni * 80;
            #pragma unroll
            for (int n = 0; n < 5; n++) {
                uint32_t bh[2], bl[2];
                ldm_x2t(bh, sb + E_WH + brow + n * 16);
                ldm_x2t(bl, sb + E_WL + brow + n * 16);
                #pragma unroll
                for (int m = 0; m < 2; m++) {
                    mma_bf16(acc[m][n], ah[m], bh);
                    mma_bf16(acc[m][n], al[m], bh);
                    mma_bf16(acc[m][n], ah[m], bl);
                }
            }
        }

        // ---- epilogue: bias + relu ----
        const int r0 = t * TILE1 + mi * 32 + (lane >> 2);
        #pragma unroll
        for (int n = 0; n < 5; n++) {
            const int col = ni * 40 + n * 8 + 2 * (lane & 3);
            const float b0 = s_bias[col], b1 = s_bias[col + 1];
            #pragma unroll
            for (int m = 0; m < 2; m++) {
                float2 o0, o1;
                o0.x = fmaxf(acc[m][n][0] + b0, 0.0f);
                o0.y = fmaxf(acc[m][n][1] + b1, 0.0f);
                o1.x = fmaxf(acc[m][n][2] + b0, 0.0f);
                o1.y = fmaxf(acc[m][n][3] + b1, 0.0f);
                *reinterpret_cast<float2*>(z_edge + (size_t)(r0 + m * 16) * 160 + col) = o0;
                *reinterpret_cast<float2*>(z_edge + (size_t)(r0 + m * 16 + 8) * 160 + col) = o1;
            }
        }
    }
}

// =====================================================================
// Kernel 2: gate branch, TILE=64, 256 threads, 2 CTAs/SM, prefetched
// =====================================================================
static __device__ __forceinline__ float lut_eval(const float2* tab, float x) {
    float tp = fmaf(x, 512.0f / 20.0f, 256.0f);    // [-10,10] -> [0,512)
    tp = fminf(fmaxf(tp, 0.0f), 511.0f);
    const int i = (int)tp;
    const float fr = tp - (float)i;
    const float2 c = tab[i];
    return fmaf(fr, c.y, c.x);
}

static __device__ __forceinline__ void gate_preload(float4* v, int ge, int q,
                                                    const float* __restrict__ z,
                                                    const int* __restrict__ srcp,
                                                    const int* __restrict__ dstp)
{
    const int node = (q < 2) ? dstp[ge] : srcp[ge];
    const float4* zr = reinterpret_cast<const float4*>(z + (size_t)node * 64) + (q & 1) * 8;
    #pragma unroll
    for (int i = 0; i < 8; i++) v[i] = zr[i];
}

__global__ __launch_bounds__(THR2, 2)
void gate_kernel(const float* __restrict__ z,
                 const int*   __restrict__ srcp,
                 const int*   __restrict__ dstp,
                 const float* __restrict__ Wf,
                 const float* __restrict__ bf,
                 const float* __restrict__ Ws,
                 const float* __restrict__ bs,
                 float* __restrict__ z_node)
{
    extern __shared__ char sm[];
    const uint32_t sb = smem_u32(sm);
    const int tid = threadIdx.x, wid = tid >> 5, lane = tid & 31;
    const int mi = wid >> 2, ni = wid & 3;   // rows mi*32; f cols ni*16, s cols 64+ni*16

    for (int idx = tid; idx < 128 * 128; idx += THR2) {
        const int k = idx >> 7, n = idx & 127;
        const float w = (n < 64) ? Wf[k * 64 + n] : Ws[k * 64 + (n - 64)];
        const __nv_bfloat16 h = __float2bfloat16(w);
        const __nv_bfloat16 l = __float2bfloat16(w - __bfloat162float(h));
        *reinterpret_cast<__nv_bfloat16*>(sm + G_WH + k * MSTRIDE + n * 2) = h;
        *reinterpret_cast<__nv_bfloat16*>(sm + G_WL + k * MSTRIDE + n * 2) = l;
    }
    for (int i = tid; i < 512; i += THR2) {
        const float x0 = -10.0f + (float)i * (20.0f / 512.0f);
        const float x1 = x0 + (20.0f / 512.0f);
        const float s0 = 1.0f / (1.0f + expf(-x0));
        const float s1 = 1.0f / (1.0f + expf(-x1));
        reinterpret_cast<float2*>(sm + G_LSIG)[i] = make_float2(s0, s1 - s0);
        const float p0 = fmaxf(x0, 0.0f) + log1pf(expf(-fabsf(x0)));
        const float p1 = fmaxf(x1, 0.0f) + log1pf(expf(-fabsf(x1)));
        reinterpret_cast<float2*>(sm + G_LSP)[i] = make_float2(p0, p1 - p0);
    }
    if (tid < 64) {
        reinterpret_cast<float*>(sm + G_BF)[tid] = bf[tid];
        reinterpret_cast<float*>(sm + G_BS)[tid] = bs[tid];
    }

    const float2* t_sig = reinterpret_cast<const float2*>(sm + G_LSIG);
    const float2* t_sp  = reinterpret_cast<const float2*>(sm + G_LSP);
    const float*  s_bf  = reinterpret_cast<const float*>(sm + G_BF);
    const float*  s_bs  = reinterpret_cast<const float*>(sm + G_BS);
    const int e_loc = tid >> 2, q = tid & 3;

    float4 v[8];
    int t = blockIdx.x;
    if (t < NT2) gate_preload(v, t * TILE2 + e_loc, q, z, srcp, dstp);

    for (; t < NT2; t += gridDim.x) {
        __syncthreads();

        // ---- STS from prefetched registers ----
        {
            uint32_t* mh = reinterpret_cast<uint32_t*>(sm + G_MH + e_loc * MSTRIDE) + q * 16;
            uint32_t* ml = reinterpret_cast<uint32_t*>(sm + G_ML + e_loc * MSTRIDE) + q * 16;
            #pragma unroll
            for (int i = 0; i < 8; i++) {
                uint32_t h0, l0, h1, l1;
                split2(v[i].x, v[i].y, h0, l0);
                split2(v[i].z, v[i].w, h1, l1);
                mh[2 * i] = h0; mh[2 * i + 1] = h1;
                ml[2 * i] = l0; ml[2 * i + 1] = l1;
            }
        }
        __syncthreads();

        const int tn = t + gridDim.x;
        if (tn < NT2) gate_preload(v, tn * TILE2 + e_loc, q, z, srcp, dstp);

        // ---- GEMM ----
        float accf[2][2][4], accs[2][2][4];
        #pragma unroll
        for (int m = 0; m < 2; m++)
            #pragma unroll
            for (int n = 0; n < 2; n++)
                #pragma unroll
                for (int r = 0; r < 4; r++) { accf[m][n][r] = 0.0f; accs[m][n][r] = 0.0f; }

        #pragma unroll 2
        for (int k = 0; k < 8; k++) {
            uint32_t ah[2][4], al[2][4];
            const uint32_t arow = (uint32_t)(mi * 32 + (lane & 15)) * MSTRIDE
                                + (uint32_t)k * 32 + ((lane >> 4) << 4);
            #pragma unroll
            for (int m = 0; m < 2; m++) {
                ldm_x4(ah[m], sb + G_MH + arow + m * 16 * MSTRIDE);
                ldm_x4(al[m], sb + G_ML + arow + m * 16 * MSTRIDE);
            }
            const uint32_t brow = (uint32_t)(k * 16 + (lane & 15)) * MSTRIDE;
            #pragma unroll
            for (int n = 0; n < 2; n++) {
                uint32_t bfh[2], bfl[2], bsh[2], bsl[2];
                const uint32_t fcol = (uint32_t)(ni * 32 + n * 16);
                ldm_x2t(bfh, sb + G_WH + brow + fcol);
                ldm_x2t(bfl, sb + G_WL + brow + fcol);
                ldm_x2t(bsh, sb + G_WH + brow + 128 + fcol);
                ldm_x2t(bsl, sb + G_WL + brow + 128 + fcol);
                #pragma unroll
                for (int m = 0; m < 2; m++) {
                    mma_bf16(accf[m][n], ah[m], bfh);
                    mma_bf16(accf[m][n], al[m], bfh);
                    mma_bf16(accf[m][n], ah[m], bfl);
                    mma_bf16(accs[m][n], ah[m], bsh);
                    mma_bf16(accs[m][n], al[m], bsh);
                    mma_bf16(accs[m][n], ah[m], bsl);
                }
            }
        }

        // ---- in-register gate + scatter ----
        #pragma unroll
        for (int m = 0; m < 2; m++) {
            const int ra = t * TILE2 + mi * 32 + m * 16 + (lane >> 2);
            const int da = dstp[ra];
            const int db = dstp[ra + 8];
            #pragma unroll
            for (int n = 0; n < 2; n++) {
                const int c = ni * 16 + n * 8 + 2 * (lane & 3);
                const float bf0 = s_bf[c], bf1 = s_bf[c + 1];
                const float bs0 = s_bs[c], bs1 = s_bs[c + 1];
                float2 m0, m1;
                m0.x = lut_eval(t_sig, accf[m][n][0] + bf0) *
                       fmaxf(lut_eval(t_sp, accs[m][n][0] + bs0), accs[m][n][0] + bs0);
                m0.y = lut_eval(t_sig, accf[m][n][1] + bf1) *
                       fmaxf(lut_eval(t_sp, accs[m][n][1] + bs1), accs[m][n][1] + bs1);
                m1.x = lut_eval(t_sig, accf[m][n][2] + bf0) *
                       fmaxf(lut_eval(t_sp, accs[m][n][2] + bs0), accs[m][n][2] + bs0);
                m1.y = lut_eval(t_sig, accf[m][n][3] + bf1) *
                       fmaxf(lut_eval(t_sp, accs[m][n][3] + bs1), accs[m][n][3] + bs1);
                atomicAdd(reinterpret_cast<float2*>(z_node + (size_t)da * 64 + c), m0);
                atomicAdd(reinterpret_cast<float2*>(z_node + (size_t)db * 64 + c), m1);
            }
        }
    }
}

extern "C" void kernel_launch(void* const* d_in, const int* in_sizes, int n_in,
                              void* d_out, int out_size)
{
    const float* z    = (const float*)d_in[0];
    const float* ea   = (const float*)d_in[1];
    const int*   eidx = (const int*)  d_in[2];
    const float* Wffw = (const float*)d_in[3];
    const float* bffw = (const float*)d_in[4];
    const float* Wf   = (const float*)d_in[5];
    const float* bf   = (const float*)d_in[6];
    const float* Ws   = (const float*)d_in[7];
    const float* bs   = (const float*)d_in[8];

    float* z_node = (float*)d_out;
    float* z_edge = (float*)d_out + (size_t)NNODE * 64;
    const int* srcp = eidx;
    const int* dstp = eidx + NE;

    cudaMemcpyAsync(z_node, z, (size_t)NNODE * 64 * sizeof(float),
                    cudaMemcpyDeviceToDevice, 0);

    cudaFuncSetAttribute(edge_mlp_kernel, cudaFuncAttributeMaxDynamicSharedMemorySize, E_SMEM);
    cudaFuncSetAttribute(gate_kernel,     cudaFuncAttributeMaxDynamicSharedMemorySize, G_SMEM);

    edge_mlp_kernel<<<148, THR1, E_SMEM, 0>>>(z, ea, srcp, dstp, Wffw, bffw, z_edge);
    gate_kernel<<<296, THR2, G_SMEM, 0>>>(z, srcp, dstp, Wf, bf, Ws, bs, z_node);
}

// round 6
// speedup vs baseline: 1.2548x; 1.1913x over previous
#include <cuda_runtime.h>
#include <cuda_bf16.h>
#include <cstdint>
#include <math.h>

#define NE      800000
#define NNODE   50000

// ---------------- scratch (static device arrays; no allocation) ----------------
__device__ float g_UV[(size_t)NNODE * 320];   // [n][0:160]=U=z@W1, [160:320]=V=z@W2
__device__ float g_G1[(size_t)NNODE * 128];   // [n][0:64]=P=z@Wf_top, [64:128]=R=z@Ws_top
__device__ float g_G2[(size_t)NNODE * 128];   // [n][0:64]=Q=z@Wf_bot, [64:128]=S=z@Ws_bot

// ---------------- kernel A (node GEMM) ----------------
#define A_THR  512
#define A_TILE 64
#define A_NT   ((NNODE + A_TILE - 1) / A_TILE)   // 782
#define A_ZSTR 144
#define A_WSTR 1168
#define A_ZH   0
#define A_ZL   (A_ZH + 64 * A_ZSTR)
#define A_WH   (A_ZL + 64 * A_ZSTR)
#define A_WL   (A_WH + 64 * A_WSTR)
#define A_SMEM (A_WL + 64 * A_WSTR)              // 167936

// ---------------- kernel B (edge assemble + ea@W3) ----------------
#define B_THR  256
#define B_TILE 64
#define B_NT   (NE / B_TILE)                     // 12500
#define B_ESTR 80
#define B_WSTR 336
#define B_EH   0
#define B_EL   (B_EH + 64 * B_ESTR)
#define B_WH   (B_EL + 64 * B_ESTR)
#define B_WL   (B_WH + 32 * B_WSTR)
#define B_BIAS (B_WL + 32 * B_WSTR)
#define B_SMEM (B_BIAS + 640)                    // 32384

static __device__ __forceinline__ uint32_t smem_u32(const void* p) {
    uint32_t a;
    asm("{ .reg .u64 t; cvta.to.shared.u64 t, %1; cvt.u32.u64 %0, t; }" : "=r"(a) : "l"(p));
    return a;
}
static __device__ __forceinline__ void ldm_x4(uint32_t* r, uint32_t addr) {
    asm volatile("ldmatrix.sync.aligned.m8n8.x4.shared.b16 {%0,%1,%2,%3}, [%4];"
                 : "=r"(r[0]), "=r"(r[1]), "=r"(r[2]), "=r"(r[3]) : "r"(addr));
}
static __device__ __forceinline__ void ldm_x2t(uint32_t* r, uint32_t addr) {
    asm volatile("ldmatrix.sync.aligned.m8n8.x2.trans.shared.b16 {%0,%1}, [%2];"
                 : "=r"(r[0]), "=r"(r[1]) : "r"(addr));
}
static __device__ __forceinline__ void mma_bf16(float* c, const uint32_t* a, const uint32_t* b) {
    asm volatile("mma.sync.aligned.m16n8k16.row.col.f32.bf16.bf16.f32 "
                 "{%0,%1,%2,%3}, {%4,%5,%6,%7}, {%8,%9}, {%0,%1,%2,%3};"
                 : "+f"(c[0]), "+f"(c[1]), "+f"(c[2]), "+f"(c[3])
                 : "r"(a[0]), "r"(a[1]), "r"(a[2]), "r"(a[3]), "r"(b[0]), "r"(b[1]));
}
static __device__ __forceinline__ void split2(float x0, float x1, uint32_t& hi, uint32_t& lo) {
    uint32_t h;
    asm("cvt.rn.bf16x2.f32 %0, %1, %2;" : "=r"(h) : "f"(x1), "f"(x0));
    float h0 = __uint_as_float(h << 16);
    float h1 = __uint_as_float(h & 0xFFFF0000u);
    uint32_t l;
    asm("cvt.rn.bf16x2.f32 %0, %1, %2;" : "=r"(l) : "f"(x1 - h1), "f"(x0 - h0));
    hi = h; lo = l;
}
static __device__ __forceinline__ float* scratch_ptr(int row, int j) {
    if (j < 320) return g_UV + (size_t)row * 320 + j;
    if (j < 448) return g_G1 + (size_t)row * 128 + (j - 320);
    return g_G2 + (size_t)row * 128 + (j - 448);
}

// =====================================================================
// Kernel A: [NNODE,64] @ BigW[64,576] -> UV | G1 | G2   (3-product bf16)
// BigW cols: 0-159 W1 (Wffw rows 0-63), 160-319 W2 (rows 64-127),
//            320-383 Wf_top, 384-447 Ws_top, 448-511 Wf_bot, 512-575 Ws_bot
// =====================================================================
__global__ __launch_bounds__(A_THR, 1)
void node_gemm_kernel(const float* __restrict__ z,
                      const float* __restrict__ Wffw,
                      const float* __restrict__ Wf,
                      const float* __restrict__ Ws)
{
    extern __shared__ char sm[];
    const uint32_t sb = smem_u32(sm);
    const int tid = threadIdx.x, wid = tid >> 5, lane = tid & 31;
    const int mi = wid >> 2, ni = wid & 3;

    // build BigW hi/lo in smem
    for (int idx = tid; idx < 64 * 576; idx += A_THR) {
        const int k = idx / 576, j = idx - k * 576;
        float w;
        if (j < 160)      w = Wffw[k * 160 + j];
        else if (j < 320) w = Wffw[(64 + k) * 160 + (j - 160)];
        else if (j < 384) w = Wf[k * 64 + (j - 320)];
        else if (j < 448) w = Ws[k * 64 + (j - 384)];
        else if (j < 512) w = Wf[(64 + k) * 64 + (j - 448)];
        else              w = Ws[(64 + k) * 64 + (j - 512)];
        const __nv_bfloat16 h = __float2bfloat16(w);
        const __nv_bfloat16 l = __float2bfloat16(w - __bfloat162float(h));
        *reinterpret_cast<__nv_bfloat16*>(sm + A_WH + k * A_WSTR + j * 2) = h;
        *reinterpret_cast<__nv_bfloat16*>(sm + A_WL + k * A_WSTR + j * 2) = l;
    }

    // gather z tile (64 rows x 64 cols), zero-padded at the tail
    const int row0 = blockIdx.x * A_TILE;
    {
        const int r = tid >> 3, cq = (tid & 7) * 8;
        const int grow = row0 + r;
        float4 a = make_float4(0.f, 0.f, 0.f, 0.f), b = a;
        if (grow < NNODE) {
            const float4* zr = reinterpret_cast<const float4*>(z + (size_t)grow * 64 + cq);
            a = zr[0]; b = zr[1];
        }
        uint32_t* zh = reinterpret_cast<uint32_t*>(sm + A_ZH + r * A_ZSTR + cq * 2);
        uint32_t* zl = reinterpret_cast<uint32_t*>(sm + A_ZL + r * A_ZSTR + cq * 2);
        uint32_t h0, l0, h1, l1;
        split2(a.x, a.y, h0, l0); split2(a.z, a.w, h1, l1);
        zh[0] = h0; zh[1] = h1; zl[0] = l0; zl[1] = l1;
        split2(b.x, b.y, h0, l0); split2(b.z, b.w, h1, l1);
        zh[2] = h0; zh[3] = h1; zl[2] = l0; zl[3] = l1;
    }
    __syncthreads();

    // GEMM: warp (mi,ni): rows mi*16 (1 m-frag), cols ni*144 (18 n8-frags)
    float acc[18][4];
    #pragma unroll
    for (int n = 0; n < 18; n++)
        #pragma unroll
        for (int r = 0; r < 4; r++) acc[n][r] = 0.0f;

    #pragma unroll
    for (int k = 0; k < 4; k++) {
        uint32_t ah[4], al[4];
        const uint32_t arow = (uint32_t)(mi * 16 + (lane & 15)) * A_ZSTR
                            + (uint32_t)k * 32 + ((lane >> 4) << 4);
        ldm_x4(ah, sb + A_ZH + arow);
        ldm_x4(al, sb + A_ZL + arow);
        const uint32_t brow = (uint32_t)(k * 16 + (lane & 15)) * A_WSTR + (uint32_t)ni * 288;
        #pragma unroll
        for (int n = 0; n < 18; n++) {
            uint32_t bh[2], bl[2];
            ldm_x2t(bh, sb + A_WH + brow + n * 16);
            ldm_x2t(bl, sb + A_WL + brow + n * 16);
            mma_bf16(acc[n], ah, bh);
            mma_bf16(acc[n], al, bh);
            mma_bf16(acc[n], ah, bl);
        }
    }

    // scatter to scratch
    const int r0 = row0 + mi * 16 + (lane >> 2);
    const int r1 = r0 + 8;
    #pragma unroll
    for (int n = 0; n < 18; n++) {
        const int j = ni * 144 + n * 8 + 2 * (lane & 3);
        if (r0 < NNODE) {
            float2 o; o.x = acc[n][0]; o.y = acc[n][1];
            *reinterpret_cast<float2*>(scratch_ptr(r0, j)) = o;
        }
        if (r1 < NNODE) {
            float2 o; o.x = acc[n][2]; o.y = acc[n][3];
            *reinterpret_cast<float2*>(scratch_ptr(r1, j)) = o;
        }
    }
}

// =====================================================================
// Kernel B: z_edge[e] = relu(U[src] + V[dst] + ea[e]@W3 + b)
// =====================================================================
__global__ __launch_bounds__(B_THR, 3)
void edge_assemble_kernel(const float* __restrict__ ea,
                          const int*   __restrict__ srcp,
                          const int*   __restrict__ dstp,
                          const float* __restrict__ Wffw,
                          const float* __restrict__ bias,
                          float* __restrict__ z_edge)
{
    extern __shared__ char sm[];
    const uint32_t sb = smem_u32(sm);
    const int tid = threadIdx.x, wid = tid >> 5, lane = tid & 31;
    const int mi = wid >> 2, ni = wid & 3;      // rows mi*32, cols ni*40

    // W3 = Wffw rows 128..159, hi/lo
    for (int idx = tid; idx < 32 * 160; idx += B_THR) {
        const int k = idx / 160, n = idx - k * 160;
        const float w = Wffw[(128 + k) * 160 + n];
        const __nv_bfloat16 h = __float2bfloat16(w);
        const __nv_bfloat16 l = __float2bfloat16(w - __bfloat162float(h));
        *reinterpret_cast<__nv_bfloat16*>(sm + B_WH + k * B_WSTR + n * 2) = h;
        *reinterpret_cast<__nv_bfloat16*>(sm + B_WL + k * B_WSTR + n * 2) = l;
    }
    if (tid < 160) reinterpret_cast<float*>(sm + B_BIAS)[tid] = bias[tid];
    const float* s_bias = reinterpret_cast<const float*>(sm + B_BIAS);

    for (int t = blockIdx.x; t < B_NT; t += gridDim.x) {
        __syncthreads();

        // gather ea tile: 64 edges x 32 cols
        {
            const int e_loc = tid >> 2, q = tid & 3;
            const int ge = t * B_TILE + e_loc;
            const float4* ep = reinterpret_cast<const float4*>(ea + (size_t)ge * 32) + q * 2;
            const float4 a = ep[0], b = ep[1];
            uint32_t* xh = reinterpret_cast<uint32_t*>(sm + B_EH + e_loc * B_ESTR + q * 16);
            uint32_t* xl = reinterpret_cast<uint32_t*>(sm + B_EL + e_loc * B_ESTR + q * 16);
            uint32_t h0, l0, h1, l1;
            split2(a.x, a.y, h0, l0); split2(a.z, a.w, h1, l1);
            xh[0] = h0; xh[1] = h1; xl[0] = l0; xl[1] = l1;
            split2(b.x, b.y, h0, l0); split2(b.z, b.w, h1, l1);
            xh[2] = h0; xh[3] = h1; xl[2] = l0; xl[3] = l1;
        }
        __syncthreads();

        // small GEMM ea@W3: K=32
        float acc[2][5][4];
        #pragma unroll
        for (int m = 0; m < 2; m++)
            #pragma unroll
            for (int n = 0; n < 5; n++)
                #pragma unroll
                for (int r = 0; r < 4; r++) acc[m][n][r] = 0.0f;

        #pragma unroll
        for (int k = 0; k < 2; k++) {
            uint32_t ah[2][4], al[2][4];
            const uint32_t arow = (uint32_t)(mi * 32 + (lane & 15)) * B_ESTR
                                + (uint32_t)k * 32 + ((lane >> 4) << 4);
            #pragma unroll
            for (int m = 0; m < 2; m++) {
                ldm_x4(ah[m], sb + B_EH + arow + m * 16 * B_ESTR);
                ldm_x4(al[m], sb + B_EL + arow + m * 16 * B_ESTR);
            }
            const uint32_t brow = (uint32_t)(k * 16 + (lane & 15)) * B_WSTR + (uint32_t)ni * 80;
            #pragma unroll
            for (int n = 0; n < 5; n++) {
                uint32_t bh[2], bl[2];
                ldm_x2t(bh, sb + B_WH + brow + n * 16);
                ldm_x2t(bl, sb + B_WL + brow + n * 16);
                #pragma unroll
                for (int m = 0; m < 2; m++) {
                    mma_bf16(acc[m][n], ah[m], bh);
                    mma_bf16(acc[m][n], al[m], bh);
                    mma_bf16(acc[m][n], ah[m], bl);
                }
            }
        }

        // epilogue: + U[src] + V[dst] + bias, relu, store
        #pragma unroll
        for (int m = 0; m < 2; m++) {
            const int r0 = t * B_TILE + mi * 32 + m * 16 + (lane >> 2);
            const int r1 = r0 + 8;
            const int s0 = srcp[r0], d0 = dstp[r0];
            const int s1 = srcp[r1], d1 = dstp[r1];
            #pragma unroll
            for (int n = 0; n < 5; n++) {
                const int j = ni * 40 + n * 8 + 2 * (lane & 3);
                const float2 u0 = *reinterpret_cast<const float2*>(g_UV + (size_t)s0 * 320 + j);
                const float2 v0 = *reinterpret_cast<const float2*>(g_UV + (size_t)d0 * 320 + 160 + j);
                const float2 u1 = *reinterpret_cast<const float2*>(g_UV + (size_t)s1 * 320 + j);
                const float2 v1 = *reinterpret_cast<const float2*>(g_UV + (size_t)d1 * 320 + 160 + j);
                const float b0 = s_bias[j], b1 = s_bias[j + 1];
                float2 o0, o1;
                o0.x = fmaxf(acc[m][n][0] + u0.x + v0.x + b0, 0.0f);
                o0.y = fmaxf(acc[m][n][1] + u0.y + v0.y + b1, 0.0f);
                o1.x = fmaxf(acc[m][n][2] + u1.x + v1.x + b0, 0.0f);
                o1.y = fmaxf(acc[m][n][3] + u1.y + v1.y + b1, 0.0f);
                *reinterpret_cast<float2*>(z_edge + (size_t)r0 * 160 + j) = o0;
                *reinterpret_cast<float2*>(z_edge + (size_t)r1 * 160 + j) = o1;
            }
        }
    }
}

// =====================================================================
// Kernel C: msg = sigmoid(P[dst]+Q[src]+bf) * softplus(R[dst]+S[src]+bs)
//           z_node[dst] += msg     (no GEMM; LUT nonlinearities)
// =====================================================================
static __device__ __forceinline__ float lut_eval(const float2* tab, float x) {
    float tp = fmaf(x, 512.0f / 20.0f, 256.0f);
    tp = fminf(fmaxf(tp, 0.0f), 511.0f);
    const int i = (int)tp;
    const float fr = tp - (float)i;
    const float2 c = tab[i];
    return fmaf(fr, c.y, c.x);
}

__global__ __launch_bounds__(256)
void gate_assemble_kernel(const int* __restrict__ srcp,
                          const int* __restrict__ dstp,
                          const float* __restrict__ bf,
                          const float* __restrict__ bs,
                          float* __restrict__ z_node)
{
    __shared__ float2 t_sig[512];
    __shared__ float2 t_sp[512];
    __shared__ float s_bf[64], s_bs[64];

    const int tid = threadIdx.x;
    for (int i = tid; i < 512; i += 256) {
        const float x0 = -10.0f + (float)i * (20.0f / 512.0f);
        const float x1 = x0 + (20.0f / 512.0f);
        const float s0 = 1.0f / (1.0f + expf(-x0));
        const float s1 = 1.0f / (1.0f + expf(-x1));
        t_sig[i] = make_float2(s0, s1 - s0);
        const float p0 = fmaxf(x0, 0.0f) + log1pf(expf(-fabsf(x0)));
        const float p1 = fmaxf(x1, 0.0f) + log1pf(expf(-fabsf(x1)));
        t_sp[i] = make_float2(p0, p1 - p0);
    }
    if (tid < 64) { s_bf[tid] = bf[tid]; s_bs[tid] = bs[tid]; }
    __syncthreads();

    const int e = blockIdx.x * 64 + (tid >> 2);
    const int c0 = (tid & 3) * 16;
    const int d = dstp[e], s = srcp[e];
    const float4* Pf = reinterpret_cast<const float4*>(g_G1 + (size_t)d * 128 + c0);
    const float4* Qf = reinterpret_cast<const float4*>(g_G2 + (size_t)s * 128 + c0);
    const float4* Ps = reinterpret_cast<const float4*>(g_G1 + (size_t)d * 128 + 64 + c0);
    const float4* Qs = reinterpret_cast<const float4*>(g_G2 + (size_t)s * 128 + 64 + c0);
    float* out = z_node + (size_t)d * 64 + c0;

    #pragma unroll
    for (int j = 0; j < 4; j++) {
        const float4 pf = Pf[j], qf = Qf[j], ps = Ps[j], qs = Qs[j];
        const int c = c0 + 4 * j;
        float4 msg;
        {
            const float f = pf.x + qf.x + s_bf[c + 0];
            const float v = ps.x + qs.x + s_bs[c + 0];
            msg.x = lut_eval(t_sig, f) * fmaxf(lut_eval(t_sp, v), v);
        }
        {
            const float f = pf.y + qf.y + s_bf[c + 1];
            const float v = ps.y + qs.y + s_bs[c + 1];
            msg.y = lut_eval(t_sig, f) * fmaxf(lut_eval(t_sp, v), v);
        }
        {
            const float f = pf.z + qf.z + s_bf[c + 2];
            const float v = ps.z + qs.z + s_bs[c + 2];
            msg.z = lut_eval(t_sig, f) * fmaxf(lut_eval(t_sp, v), v);
        }
        {
            const float f = pf.w + qf.w + s_bf[c + 3];
            const float v = ps.w + qs.w + s_bs[c + 3];
            msg.w = lut_eval(t_sig, f) * fmaxf(lut_eval(t_sp, v), v);
        }
        atomicAdd(reinterpret_cast<float4*>(out + 4 * j), msg);
    }
}

extern "C" void kernel_launch(void* const* d_in, const int* in_sizes, int n_in,
                              void* d_out, int out_size)
{
    const float* z    = (const float*)d_in[0];
    const float* ea   = (const float*)d_in[1];
    const int*   eidx = (const int*)  d_in[2];
    const float* Wffw = (const float*)d_in[3];
    const float* bffw = (const float*)d_in[4];
    const float* Wf   = (const float*)d_in[5];
    const float* bf   = (const float*)d_in[6];
    const float* Ws   = (const float*)d_in[7];
    const float* bs   = (const float*)d_in[8];

    float* z_node = (float*)d_out;
    float* z_edge = (float*)d_out + (size_t)NNODE * 64;
    const int* srcp = eidx;
    const int* dstp = eidx + NE;

    // residual base for scatter-add
    cudaMemcpyAsync(z_node, z, (size_t)NNODE * 64 * sizeof(float),
                    cudaMemcpyDeviceToDevice, 0);

    cudaFuncSetAttribute(node_gemm_kernel, cudaFuncAttributeMaxDynamicSharedMemorySize, A_SMEM);
    cudaFuncSetAttribute(edge_assemble_kernel, cudaFuncAttributeMaxDynamicSharedMemorySize, B_SMEM);

    node_gemm_kernel<<<A_NT, A_THR, A_SMEM, 0>>>(z, Wffw, Wf, Ws);
    edge_assemble_kernel<<<444, B_THR, B_SMEM, 0>>>(ea, srcp, dstp, Wffw, bffw, z_edge);
    gate_assemble_kernel<<<B_NT, 256, 0, 0>>>(srcp, dstp, bf, bs, z_node);
}

// round 7
// speedup vs baseline: 1.4435x; 1.1504x over previous
#include <cuda_runtime.h>
#include <cuda_bf16.h>
#include <cstdint>
#include <math.h>

#define NE      800000
#define NNODE   50000

// ---------------- scratch (static device arrays; no allocation) ----------------
__device__ float g_UV[(size_t)NNODE * 320];   // [n][0:160]=U=z@W1, [160:320]=V=z@W2
__device__ float g_G1[(size_t)NNODE * 128];   // [n][0:64]=P=z@Wf_top, [64:128]=R=z@Ws_top
__device__ float g_G2[(size_t)NNODE * 128];   // [n][0:64]=Q=z@Wf_bot, [64:128]=S=z@Ws_bot

// ---------------- kernel A (node GEMM, persistent) ----------------
#define A_THR  512
#define A_TILE 64
#define A_NT   ((NNODE + A_TILE - 1) / A_TILE)   // 782
#define A_ZSTR 144
#define A_WSTR 1168
#define A_ZH   0
#define A_ZL   (A_ZH + 64 * A_ZSTR)
#define A_WH   (A_ZL + 64 * A_ZSTR)
#define A_WL   (A_WH + 64 * A_WSTR)
#define A_SMEM (A_WL + 64 * A_WSTR)              // 167936

// ---------------- kernel B (edge assemble + ea@W3) ----------------
#define B_THR  256
#define B_TILE 64
#define B_NT   (NE / B_TILE)                     // 12500
#define B_ESTR 80
#define B_WSTR 336
#define B_EH   0
#define B_EL   (B_EH + 64 * B_ESTR)
#define B_WH   (B_EL + 64 * B_ESTR)
#define B_WL   (B_WH + 32 * B_WSTR)
#define B_BIAS (B_WL + 32 * B_WSTR)
#define B_SMEM (B_BIAS + 640)                    // 32384

static __device__ __forceinline__ uint32_t smem_u32(const void* p) {
    uint32_t a;
    asm("{ .reg .u64 t; cvta.to.shared.u64 t, %1; cvt.u32.u64 %0, t; }" : "=r"(a) : "l"(p));
    return a;
}
static __device__ __forceinline__ void ldm_x4(uint32_t* r, uint32_t addr) {
    asm volatile("ldmatrix.sync.aligned.m8n8.x4.shared.b16 {%0,%1,%2,%3}, [%4];"
                 : "=r"(r[0]), "=r"(r[1]), "=r"(r[2]), "=r"(r[3]) : "r"(addr));
}
static __device__ __forceinline__ void ldm_x2t(uint32_t* r, uint32_t addr) {
    asm volatile("ldmatrix.sync.aligned.m8n8.x2.trans.shared.b16 {%0,%1}, [%2];"
                 : "=r"(r[0]), "=r"(r[1]) : "r"(addr));
}
static __device__ __forceinline__ void mma_bf16(float* c, const uint32_t* a, const uint32_t* b) {
    asm volatile("mma.sync.aligned.m16n8k16.row.col.f32.bf16.bf16.f32 "
                 "{%0,%1,%2,%3}, {%4,%5,%6,%7}, {%8,%9}, {%0,%1,%2,%3};"
                 : "+f"(c[0]), "+f"(c[1]), "+f"(c[2]), "+f"(c[3])
                 : "r"(a[0]), "r"(a[1]), "r"(a[2]), "r"(a[3]), "r"(b[0]), "r"(b[1]));
}
static __device__ __forceinline__ void split2(float x0, float x1, uint32_t& hi, uint32_t& lo) {
    uint32_t h;
    asm("cvt.rn.bf16x2.f32 %0, %1, %2;" : "=r"(h) : "f"(x1), "f"(x0));
    float h0 = __uint_as_float(h << 16);
    float h1 = __uint_as_float(h & 0xFFFF0000u);
    uint32_t l;
    asm("cvt.rn.bf16x2.f32 %0, %1, %2;" : "=r"(l) : "f"(x1 - h1), "f"(x0 - h0));
    hi = h; lo = l;
}
static __device__ __forceinline__ float* scratch_ptr(int row, int j) {
    if (j < 320) return g_UV + (size_t)row * 320 + j;
    if (j < 448) return g_G1 + (size_t)row * 128 + (j - 320);
    return g_G2 + (size_t)row * 128 + (j - 448);
}

// =====================================================================
// Kernel A (persistent): [NNODE,64] @ BigW[64,576] -> UV | G1 | G2
// BigW cols: 0-159 W1 (Wffw rows 0-63), 160-319 W2 (rows 64-127),
//            320-383 Wf_top, 384-447 Ws_top, 448-511 Wf_bot, 512-575 Ws_bot
// =====================================================================
__global__ __launch_bounds__(A_THR, 1)
void node_gemm_kernel(const float* __restrict__ z,
                      const float* __restrict__ Wffw,
                      const float* __restrict__ Wf,
                      const float* __restrict__ Ws)
{
    extern __shared__ char sm[];
    const uint32_t sb = smem_u32(sm);
    const int tid = threadIdx.x, wid = tid >> 5, lane = tid & 31;
    const int mi = wid >> 2, ni = wid & 3;

    // build BigW hi/lo in smem (ONCE per CTA; amortized over ~5.3 tiles)
    for (int idx = tid; idx < 64 * 576; idx += A_THR) {
        const int k = idx / 576, j = idx - k * 576;
        float w;
        if (j < 160)      w = Wffw[k * 160 + j];
        else if (j < 320) w = Wffw[(64 + k) * 160 + (j - 160)];
        else if (j < 384) w = Wf[k * 64 + (j - 320)];
        else if (j < 448) w = Ws[k * 64 + (j - 384)];
        else if (j < 512) w = Wf[(64 + k) * 64 + (j - 448)];
        else              w = Ws[(64 + k) * 64 + (j - 512)];
        const __nv_bfloat16 h = __float2bfloat16(w);
        const __nv_bfloat16 l = __float2bfloat16(w - __bfloat162float(h));
        *reinterpret_cast<__nv_bfloat16*>(sm + A_WH + k * A_WSTR + j * 2) = h;
        *reinterpret_cast<__nv_bfloat16*>(sm + A_WL + k * A_WSTR + j * 2) = l;
    }

    const int r = tid >> 3, cq = (tid & 7) * 8;   // z-gather: 8 threads/row

    // prefetch first tile
    float4 va = make_float4(0.f, 0.f, 0.f, 0.f), vb = va;
    int t = blockIdx.x;
    if (t < A_NT) {
        const int grow = t * A_TILE + r;
        if (grow < NNODE) {
            const float4* zr = reinterpret_cast<const float4*>(z + (size_t)grow * 64 + cq);
            va = zr[0]; vb = zr[1];
        }
    }

    for (; t < A_NT; t += gridDim.x) {
        __syncthreads();   // weights ready (1st iter) / prev tile consumed

        // STS z tile from prefetched registers
        {
            uint32_t* zh = reinterpret_cast<uint32_t*>(sm + A_ZH + r * A_ZSTR + cq * 2);
            uint32_t* zl = reinterpret_cast<uint32_t*>(sm + A_ZL + r * A_ZSTR + cq * 2);
            uint32_t h0, l0, h1, l1;
            split2(va.x, va.y, h0, l0); split2(va.z, va.w, h1, l1);
            zh[0] = h0; zh[1] = h1; zl[0] = l0; zl[1] = l1;
            split2(vb.x, vb.y, h0, l0); split2(vb.z, vb.w, h1, l1);
            zh[2] = h0; zh[3] = h1; zl[2] = l0; zl[3] = l1;
        }
        __syncthreads();

        // prefetch next tile during GEMM
        const int tn = t + gridDim.x;
        va = make_float4(0.f, 0.f, 0.f, 0.f); vb = va;
        if (tn < A_NT) {
            const int grow = tn * A_TILE + r;
            if (grow < NNODE) {
                const float4* zr = reinterpret_cast<const float4*>(z + (size_t)grow * 64 + cq);
                va = zr[0]; vb = zr[1];
            }
        }

        // GEMM: warp (mi,ni): rows mi*16, cols ni*144 (18 n8-frags)
        float acc[18][4];
        #pragma unroll
        for (int n = 0; n < 18; n++)
            #pragma unroll
            for (int q = 0; q < 4; q++) acc[n][q] = 0.0f;

        #pragma unroll
        for (int k = 0; k < 4; k++) {
            uint32_t ah[4], al[4];
            const uint32_t arow = (uint32_t)(mi * 16 + (lane & 15)) * A_ZSTR
                                + (uint32_t)k * 32 + ((lane >> 4) << 4);
            ldm_x4(ah, sb + A_ZH + arow);
            ldm_x4(al, sb + A_ZL + arow);
            const uint32_t brow = (uint32_t)(k * 16 + (lane & 15)) * A_WSTR + (uint32_t)ni * 288;
            #pragma unroll
            for (int n = 0; n < 18; n++) {
                uint32_t bh[2], bl[2];
                ldm_x2t(bh, sb + A_WH + brow + n * 16);
                ldm_x2t(bl, sb + A_WL + brow + n * 16);
                mma_bf16(acc[n], ah, bh);
                mma_bf16(acc[n], al, bh);
                mma_bf16(acc[n], ah, bl);
            }
        }

        // scatter to scratch
        const int r0 = t * A_TILE + mi * 16 + (lane >> 2);
        const int r1 = r0 + 8;
        #pragma unroll
        for (int n = 0; n < 18; n++) {
            const int j = ni * 144 + n * 8 + 2 * (lane & 3);
            if (r0 < NNODE) {
                float2 o; o.x = acc[n][0]; o.y = acc[n][1];
                *reinterpret_cast<float2*>(scratch_ptr(r0, j)) = o;
            }
            if (r1 < NNODE) {
                float2 o; o.x = acc[n][2]; o.y = acc[n][3];
                *reinterpret_cast<float2*>(scratch_ptr(r1, j)) = o;
            }
        }
    }
}

// =====================================================================
// Kernel B: z_edge[e] = relu(U[src] + V[dst] + ea[e]@W3 + b)
// =====================================================================
__global__ __launch_bounds__(B_THR, 3)
void edge_assemble_kernel(const float* __restrict__ ea,
                          const int*   __restrict__ srcp,
                          const int*   __restrict__ dstp,
                          const float* __restrict__ Wffw,
                          const float* __restrict__ bias,
                          float* __restrict__ z_edge)
{
    extern __shared__ char sm[];
    const uint32_t sb = smem_u32(sm);
    const int tid = threadIdx.x, wid = tid >> 5, lane = tid & 31;
    const int mi = wid >> 2, ni = wid & 3;      // rows mi*32, cols ni*40

    // W3 = Wffw rows 128..159, hi/lo
    for (int idx = tid; idx < 32 * 160; idx += B_THR) {
        const int k = idx / 160, n = idx - k * 160;
        const float w = Wffw[(128 + k) * 160 + n];
        const __nv_bfloat16 h = __float2bfloat16(w);
        const __nv_bfloat16 l = __float2bfloat16(w - __bfloat162float(h));
        *reinterpret_cast<__nv_bfloat16*>(sm + B_WH + k * B_WSTR + n * 2) = h;
        *reinterpret_cast<__nv_bfloat16*>(sm + B_WL + k * B_WSTR + n * 2) = l;
    }
    if (tid < 160) reinterpret_cast<float*>(sm + B_BIAS)[tid] = bias[tid];
    const float* s_bias = reinterpret_cast<const float*>(sm + B_BIAS);

    for (int t = blockIdx.x; t < B_NT; t += gridDim.x) {
        __syncthreads();

        // gather ea tile: 64 edges x 32 cols
        {
            const int e_loc = tid >> 2, q = tid & 3;
            const int ge = t * B_TILE + e_loc;
            const float4* ep = reinterpret_cast<const float4*>(ea + (size_t)ge * 32) + q * 2;
            const float4 a = ep[0], b = ep[1];
            uint32_t* xh = reinterpret_cast<uint32_t*>(sm + B_EH + e_loc * B_ESTR + q * 16);
            uint32_t* xl = reinterpret_cast<uint32_t*>(sm + B_EL + e_loc * B_ESTR + q * 16);
            uint32_t h0, l0, h1, l1;
            split2(a.x, a.y, h0, l0); split2(a.z, a.w, h1, l1);
            xh[0] = h0; xh[1] = h1; xl[0] = l0; xl[1] = l1;
            split2(b.x, b.y, h0, l0); split2(b.z, b.w, h1, l1);
            xh[2] = h0; xh[3] = h1; xl[2] = l0; xl[3] = l1;
        }
        __syncthreads();

        // small GEMM ea@W3: K=32
        float acc[2][5][4];
        #pragma unroll
        for (int m = 0; m < 2; m++)
            #pragma unroll
            for (int n = 0; n < 5; n++)
                #pragma unroll
                for (int r = 0; r < 4; r++) acc[m][n][r] = 0.0f;

        #pragma unroll
        for (int k = 0; k < 2; k++) {
            uint32_t ah[2][4], al[2][4];
            const uint32_t arow = (uint32_t)(mi * 32 + (lane & 15)) * B_ESTR
                                + (uint32_t)k * 32 + ((lane >> 4) << 4);
            #pragma unroll
            for (int m = 0; m < 2; m++) {
                ldm_x4(ah[m], sb + B_EH + arow + m * 16 * B_ESTR);
                ldm_x4(al[m], sb + B_EL + arow + m * 16 * B_ESTR);
            }
            const uint32_t brow = (uint32_t)(k * 16 + (lane & 15)) * B_WSTR + (uint32_t)ni * 80;
            #pragma unroll
            for (int n = 0; n < 5; n++) {
                uint32_t bh[2], bl[2];
                ldm_x2t(bh, sb + B_WH + brow + n * 16);
                ldm_x2t(bl, sb + B_WL + brow + n * 16);
                #pragma unroll
                for (int m = 0; m < 2; m++) {
                    mma_bf16(acc[m][n], ah[m], bh);
                    mma_bf16(acc[m][n], al[m], bh);
                    mma_bf16(acc[m][n], ah[m], bl);
                }
            }
        }

        // epilogue: + U[src] + V[dst] + bias, relu, store
        #pragma unroll
        for (int m = 0; m < 2; m++) {
            const int r0 = t * B_TILE + mi * 32 + m * 16 + (lane >> 2);
            const int r1 = r0 + 8;
            const int s0 = srcp[r0], d0 = dstp[r0];
            const int s1 = srcp[r1], d1 = dstp[r1];
            #pragma unroll
            for (int n = 0; n < 5; n++) {
                const int j = ni * 40 + n * 8 + 2 * (lane & 3);
                const float2 u0 = *reinterpret_cast<const float2*>(g_UV + (size_t)s0 * 320 + j);
                const float2 v0 = *reinterpret_cast<const float2*>(g_UV + (size_t)d0 * 320 + 160 + j);
                const float2 u1 = *reinterpret_cast<const float2*>(g_UV + (size_t)s1 * 320 + j);
                const float2 v1 = *reinterpret_cast<const float2*>(g_UV + (size_t)d1 * 320 + 160 + j);
                const float b0 = s_bias[j], b1 = s_bias[j + 1];
                float2 o0, o1;
                o0.x = fmaxf(acc[m][n][0] + u0.x + v0.x + b0, 0.0f);
                o0.y = fmaxf(acc[m][n][1] + u0.y + v0.y + b1, 0.0f);
                o1.x = fmaxf(acc[m][n][2] + u1.x + v1.x + b0, 0.0f);
                o1.y = fmaxf(acc[m][n][3] + u1.y + v1.y + b1, 0.0f);
                *reinterpret_cast<float2*>(z_edge + (size_t)r0 * 160 + j) = o0;
                *reinterpret_cast<float2*>(z_edge + (size_t)r1 * 160 + j) = o1;
            }
        }
    }
}

// =====================================================================
// Kernel C: msg = sigmoid(P[dst]+Q[src]+bf) * softplus(R[dst]+S[src]+bs)
//           z_node[dst] += msg     (no GEMM; LUT nonlinearities)
// =====================================================================
static __device__ __forceinline__ float lut_eval(const float2* tab, float x) {
    float tp = fmaf(x, 512.0f / 20.0f, 256.0f);
    tp = fminf(fmaxf(tp, 0.0f), 511.0f);
    const int i = (int)tp;
    const float fr = tp - (float)i;
    const float2 c = tab[i];
    return fmaf(fr, c.y, c.x);
}

__global__ __launch_bounds__(256)
void gate_assemble_kernel(const int* __restrict__ srcp,
                          const int* __restrict__ dstp,
                          const float* __restrict__ bf,
                          const float* __restrict__ bs,
                          float* __restrict__ z_node)
{
    __shared__ float2 t_sig[512];
    __shared__ float2 t_sp[512];
    __shared__ float s_bf[64], s_bs[64];

    const int tid = threadIdx.x;
    for (int i = tid; i < 512; i += 256) {
        const float x0 = -10.0f + (float)i * (20.0f / 512.0f);
        const float x1 = x0 + (20.0f / 512.0f);
        const float s0 = 1.0f / (1.0f + expf(-x0));
        const float s1 = 1.0f / (1.0f + expf(-x1));
        t_sig[i] = make_float2(s0, s1 - s0);
        const float p0 = fmaxf(x0, 0.0f) + log1pf(expf(-fabsf(x0)));
        const float p1 = fmaxf(x1, 0.0f) + log1pf(expf(-fabsf(x1)));
        t_sp[i] = make_float2(p0, p1 - p0);
    }
    if (tid < 64) { s_bf[tid] = bf[tid]; s_bs[tid] = bs[tid]; }
    __syncthreads();

    const int e = blockIdx.x * 64 + (tid >> 2);
    const int c0 = (tid & 3) * 16;
    const int d = dstp[e], s = srcp[e];
    const float4* Pf = reinterpret_cast<const float4*>(g_G1 + (size_t)d * 128 + c0);
    const float4* Qf = reinterpret_cast<const float4*>(g_G2 + (size_t)s * 128 + c0);
    const float4* Ps = reinterpret_cast<const float4*>(g_G1 + (size_t)d * 128 + 64 + c0);
    const float4* Qs = reinterpret_cast<const float4*>(g_G2 + (size_t)s * 128 + 64 + c0);
    float* out = z_node + (size_t)d * 64 + c0;

    #pragma unroll
    for (int j = 0; j < 4; j++) {
        const float4 pf = Pf[j], qf = Qf[j], ps = Ps[j], qs = Qs[j];
        const int c = c0 + 4 * j;
        float4 msg;
        {
            const float f = pf.x + qf.x + s_bf[c + 0];
            const float v = ps.x + qs.x + s_bs[c + 0];
            msg.x = lut_eval(t_sig, f) * fmaxf(lut_eval(t_sp, v), v);
        }
        {
            const float f = pf.y + qf.y + s_bf[c + 1];
            const float v = ps.y + qs.y + s_bs[c + 1];
            msg.y = lut_eval(t_sig, f) * fmaxf(lut_eval(t_sp, v), v);
        }
        {
            const float f = pf.z + qf.z + s_bf[c + 2];
            const float v = ps.z + qs.z + s_bs[c + 2];
            msg.z = lut_eval(t_sig, f) * fmaxf(lut_eval(t_sp, v), v);
        }
        {
            const float f = pf.w + qf.w + s_bf[c + 3];
            const float v = ps.w + qs.w + s_bs[c + 3];
            msg.w = lut_eval(t_sig, f) * fmaxf(lut_eval(t_sp, v), v);
        }
        atomicAdd(reinterpret_cast<float4*>(out + 4 * j), msg);
    }
}

extern "C" void kernel_launch(void* const* d_in, const int* in_sizes, int n_in,
                              void* d_out, int out_size)
{
    const float* z    = (const float*)d_in[0];
    const float* ea   = (const float*)d_in[1];
    const int*   eidx = (const int*)  d_in[2];
    const float* Wffw = (const float*)d_in[3];
    const float* bffw = (const float*)d_in[4];
    const float* Wf   = (const float*)d_in[5];
    const float* bf   = (const float*)d_in[6];
    const float* Ws   = (const float*)d_in[7];
    const float* bs   = (const float*)d_in[8];

    float* z_node = (float*)d_out;
    float* z_edge = (float*)d_out + (size_t)NNODE * 64;
    const int* srcp = eidx;
    const int* dstp = eidx + NE;

    // residual base for scatter-add
    cudaMemcpyAsync(z_node, z, (size_t)NNODE * 64 * sizeof(float),
                    cudaMemcpyDeviceToDevice, 0);

    cudaFuncSetAttribute(node_gemm_kernel, cudaFuncAttributeMaxDynamicSharedMemorySize, A_SMEM);
    cudaFuncSetAttribute(edge_assemble_kernel, cudaFuncAttributeMaxDynamicSharedMemorySize, B_SMEM);

    node_gemm_kernel<<<148, A_THR, A_SMEM, 0>>>(z, Wffw, Wf, Ws);
    edge_assemble_kernel<<<444, B_THR, B_SMEM, 0>>>(ea, srcp, dstp, Wffw, bffw, z_edge);
    gate_assemble_kernel<<<B_NT, 256, 0, 0>>>(srcp, dstp, bf, bs, z_node);
}

// round 8
// speedup vs baseline: 1.4713x; 1.0192x over previous
#include <cuda_runtime.h>
#include <cuda_bf16.h>
#include <cstdint>
#include <math.h>

#define NE      800000
#define NNODE   50000

// ---------------- scratch (static device arrays; no allocation) ----------------
__device__ float g_UV[(size_t)NNODE * 320];   // [n][0:160]=U=z@W1, [160:320]=V=z@W2
__device__ float g_G1[(size_t)NNODE * 128];   // [n][0:64]=P=z@Wf_top, [64:128]=R=z@Ws_top
__device__ float g_G2[(size_t)NNODE * 128];   // [n][0:64]=Q=z@Wf_bot, [64:128]=S=z@Ws_bot

// ---------------- kernel A (node GEMM, persistent) ----------------
#define A_THR  512
#define A_TILE 64
#define A_NT   ((NNODE + A_TILE - 1) / A_TILE)   // 782
#define A_ZSTR 144
#define A_WSTR 1168
#define A_ZH   0
#define A_ZL   (A_ZH + 64 * A_ZSTR)
#define A_WH   (A_ZL + 64 * A_ZSTR)
#define A_WL   (A_WH + 64 * A_WSTR)
#define A_SMEM (A_WL + 64 * A_WSTR)              // 167936

// ---------------- kernel B (edge assemble + ea@W3) ----------------
#define B_THR  256
#define B_TILE 64
#define B_NT   (NE / B_TILE)                     // 12500
#define B_ESTR 80
#define B_WSTR 336
#define B_EH   0
#define B_EL   (B_EH + 64 * B_ESTR)
#define B_WH   (B_EL + 64 * B_ESTR)
#define B_WL   (B_WH + 32 * B_WSTR)
#define B_BIAS (B_WL + 32 * B_WSTR)
#define B_SMEM (B_BIAS + 640)                    // 32384

static __device__ __forceinline__ uint32_t smem_u32(const void* p) {
    uint32_t a;
    asm("{ .reg .u64 t; cvta.to.shared.u64 t, %1; cvt.u32.u64 %0, t; }" : "=r"(a) : "l"(p));
    return a;
}
static __device__ __forceinline__ void ldm_x4(uint32_t* r, uint32_t addr) {
    asm volatile("ldmatrix.sync.aligned.m8n8.x4.shared.b16 {%0,%1,%2,%3}, [%4];"
                 : "=r"(r[0]), "=r"(r[1]), "=r"(r[2]), "=r"(r[3]) : "r"(addr));
}
static __device__ __forceinline__ void ldm_x2t(uint32_t* r, uint32_t addr) {
    asm volatile("ldmatrix.sync.aligned.m8n8.x2.trans.shared.b16 {%0,%1}, [%2];"
                 : "=r"(r[0]), "=r"(r[1]) : "r"(addr));
}
static __device__ __forceinline__ void mma_bf16(float* c, const uint32_t* a, const uint32_t* b) {
    asm volatile("mma.sync.aligned.m16n8k16.row.col.f32.bf16.bf16.f32 "
                 "{%0,%1,%2,%3}, {%4,%5,%6,%7}, {%8,%9}, {%0,%1,%2,%3};"
                 : "+f"(c[0]), "+f"(c[1]), "+f"(c[2]), "+f"(c[3])
                 : "r"(a[0]), "r"(a[1]), "r"(a[2]), "r"(a[3]), "r"(b[0]), "r"(b[1]));
}
static __device__ __forceinline__ void split2(float x0, float x1, uint32_t& hi, uint32_t& lo) {
    uint32_t h;
    asm("cvt.rn.bf16x2.f32 %0, %1, %2;" : "=r"(h) : "f"(x1), "f"(x0));
    float h0 = __uint_as_float(h << 16);
    float h1 = __uint_as_float(h & 0xFFFF0000u);
    uint32_t l;
    asm("cvt.rn.bf16x2.f32 %0, %1, %2;" : "=r"(l) : "f"(x1 - h1), "f"(x0 - h0));
    hi = h; lo = l;
}
static __device__ __forceinline__ float* scratch_ptr(int row, int j) {
    if (j < 320) return g_UV + (size_t)row * 320 + j;
    if (j < 448) return g_G1 + (size_t)row * 128 + (j - 320);
    return g_G2 + (size_t)row * 128 + (j - 448);
}

// =====================================================================
// Kernel A (persistent): [NNODE,64] @ BigW[64,576] -> UV | G1 | G2
// =====================================================================
__global__ __launch_bounds__(A_THR, 1)
void node_gemm_kernel(const float* __restrict__ z,
                      const float* __restrict__ Wffw,
                      const float* __restrict__ Wf,
                      const float* __restrict__ Ws)
{
    extern __shared__ char sm[];
    const uint32_t sb = smem_u32(sm);
    const int tid = threadIdx.x, wid = tid >> 5, lane = tid & 31;
    const int mi = wid >> 2, ni = wid & 3;

    // build BigW hi/lo in smem (ONCE per CTA)
    for (int idx = tid; idx < 64 * 576; idx += A_THR) {
        const int k = idx / 576, j = idx - k * 576;
        float w;
        if (j < 160)      w = Wffw[k * 160 + j];
        else if (j < 320) w = Wffw[(64 + k) * 160 + (j - 160)];
        else if (j < 384) w = Wf[k * 64 + (j - 320)];
        else if (j < 448) w = Ws[k * 64 + (j - 384)];
        else if (j < 512) w = Wf[(64 + k) * 64 + (j - 448)];
        else              w = Ws[(64 + k) * 64 + (j - 512)];
        const __nv_bfloat16 h = __float2bfloat16(w);
        const __nv_bfloat16 l = __float2bfloat16(w - __bfloat162float(h));
        *reinterpret_cast<__nv_bfloat16*>(sm + A_WH + k * A_WSTR + j * 2) = h;
        *reinterpret_cast<__nv_bfloat16*>(sm + A_WL + k * A_WSTR + j * 2) = l;
    }

    const int r = tid >> 3, cq = (tid & 7) * 8;

    float4 va = make_float4(0.f, 0.f, 0.f, 0.f), vb = va;
    int t = blockIdx.x;
    if (t < A_NT) {
        const int grow = t * A_TILE + r;
        if (grow < NNODE) {
            const float4* zr = reinterpret_cast<const float4*>(z + (size_t)grow * 64 + cq);
            va = zr[0]; vb = zr[1];
        }
    }

    for (; t < A_NT; t += gridDim.x) {
        __syncthreads();

        {
            uint32_t* zh = reinterpret_cast<uint32_t*>(sm + A_ZH + r * A_ZSTR + cq * 2);
            uint32_t* zl = reinterpret_cast<uint32_t*>(sm + A_ZL + r * A_ZSTR + cq * 2);
            uint32_t h0, l0, h1, l1;
            split2(va.x, va.y, h0, l0); split2(va.z, va.w, h1, l1);
            zh[0] = h0; zh[1] = h1; zl[0] = l0; zl[1] = l1;
            split2(vb.x, vb.y, h0, l0); split2(vb.z, vb.w, h1, l1);
            zh[2] = h0; zh[3] = h1; zl[2] = l0; zl[3] = l1;
        }
        __syncthreads();

        const int tn = t + gridDim.x;
        va = make_float4(0.f, 0.f, 0.f, 0.f); vb = va;
        if (tn < A_NT) {
            const int grow = tn * A_TILE + r;
            if (grow < NNODE) {
                const float4* zr = reinterpret_cast<const float4*>(z + (size_t)grow * 64 + cq);
                va = zr[0]; vb = zr[1];
            }
        }

        float acc[18][4];
        #pragma unroll
        for (int n = 0; n < 18; n++)
            #pragma unroll
            for (int q = 0; q < 4; q++) acc[n][q] = 0.0f;

        #pragma unroll
        for (int k = 0; k < 4; k++) {
            uint32_t ah[4], al[4];
            const uint32_t arow = (uint32_t)(mi * 16 + (lane & 15)) * A_ZSTR
                                + (uint32_t)k * 32 + ((lane >> 4) << 4);
            ldm_x4(ah, sb + A_ZH + arow);
            ldm_x4(al, sb + A_ZL + arow);
            const uint32_t brow = (uint32_t)(k * 16 + (lane & 15)) * A_WSTR + (uint32_t)ni * 288;
            #pragma unroll
            for (int n = 0; n < 18; n++) {
                uint32_t bh[2], bl[2];
                ldm_x2t(bh, sb + A_WH + brow + n * 16);
                ldm_x2t(bl, sb + A_WL + brow + n * 16);
                mma_bf16(acc[n], ah, bh);
                mma_bf16(acc[n], al, bh);
                mma_bf16(acc[n], ah, bl);
            }
        }

        const int r0 = t * A_TILE + mi * 16 + (lane >> 2);
        const int r1 = r0 + 8;
        #pragma unroll
        for (int n = 0; n < 18; n++) {
            const int j = ni * 144 + n * 8 + 2 * (lane & 3);
            if (r0 < NNODE) {
                float2 o; o.x = acc[n][0]; o.y = acc[n][1];
                *reinterpret_cast<float2*>(scratch_ptr(r0, j)) = o;
            }
            if (r1 < NNODE) {
                float2 o; o.x = acc[n][2]; o.y = acc[n][3];
                *reinterpret_cast<float2*>(scratch_ptr(r1, j)) = o;
            }
        }
    }
}

// =====================================================================
// Kernel B: z_edge[e] = relu(U[src] + V[dst] + ea[e]@W3 + b)
// =====================================================================
__global__ __launch_bounds__(B_THR, 3)
void edge_assemble_kernel(const float* __restrict__ ea,
                          const int*   __restrict__ srcp,
                          const int*   __restrict__ dstp,
                          const float* __restrict__ Wffw,
                          const float* __restrict__ bias,
                          float* __restrict__ z_edge)
{
    extern __shared__ char sm[];
    const uint32_t sb = smem_u32(sm);
    const int tid = threadIdx.x, wid = tid >> 5, lane = tid & 31;
    const int mi = wid >> 2, ni = wid & 3;

    for (int idx = tid; idx < 32 * 160; idx += B_THR) {
        const int k = idx / 160, n = idx - k * 160;
        const float w = Wffw[(128 + k) * 160 + n];
        const __nv_bfloat16 h = __float2bfloat16(w);
        const __nv_bfloat16 l = __float2bfloat16(w - __bfloat162float(h));
        *reinterpret_cast<__nv_bfloat16*>(sm + B_WH + k * B_WSTR + n * 2) = h;
        *reinterpret_cast<__nv_bfloat16*>(sm + B_WL + k * B_WSTR + n * 2) = l;
    }
    if (tid < 160) reinterpret_cast<float*>(sm + B_BIAS)[tid] = bias[tid];
    const float* s_bias = reinterpret_cast<const float*>(sm + B_BIAS);

    for (int t = blockIdx.x; t < B_NT; t += gridDim.x) {
        __syncthreads();

        {
            const int e_loc = tid >> 2, q = tid & 3;
            const int ge = t * B_TILE + e_loc;
            const float4* ep = reinterpret_cast<const float4*>(ea + (size_t)ge * 32) + q * 2;
            const float4 a = ep[0], b = ep[1];
            uint32_t* xh = reinterpret_cast<uint32_t*>(sm + B_EH + e_loc * B_ESTR + q * 16);
            uint32_t* xl = reinterpret_cast<uint32_t*>(sm + B_EL + e_loc * B_ESTR + q * 16);
            uint32_t h0, l0, h1, l1;
            split2(a.x, a.y, h0, l0); split2(a.z, a.w, h1, l1);
            xh[0] = h0; xh[1] = h1; xl[0] = l0; xl[1] = l1;
            split2(b.x, b.y, h0, l0); split2(b.z, b.w, h1, l1);
            xh[2] = h0; xh[3] = h1; xl[2] = l0; xl[3] = l1;
        }
        __syncthreads();

        float acc[2][5][4];
        #pragma unroll
        for (int m = 0; m < 2; m++)
            #pragma unroll
            for (int n = 0; n < 5; n++)
                #pragma unroll
                for (int r = 0; r < 4; r++) acc[m][n][r] = 0.0f;

        #pragma unroll
        for (int k = 0; k < 2; k++) {
            uint32_t ah[2][4], al[2][4];
            const uint32_t arow = (uint32_t)(mi * 32 + (lane & 15)) * B_ESTR
                                + (uint32_t)k * 32 + ((lane >> 4) << 4);
            #pragma unroll
            for (int m = 0; m < 2; m++) {
                ldm_x4(ah[m], sb + B_EH + arow + m * 16 * B_ESTR);
                ldm_x4(al[m], sb + B_EL + arow + m * 16 * B_ESTR);
            }
            const uint32_t brow = (uint32_t)(k * 16 + (lane & 15)) * B_WSTR + (uint32_t)ni * 80;
            #pragma unroll
            for (int n = 0; n < 5; n++) {
                uint32_t bh[2], bl[2];
                ldm_x2t(bh, sb + B_WH + brow + n * 16);
                ldm_x2t(bl, sb + B_WL + brow + n * 16);
                #pragma unroll
                for (int m = 0; m < 2; m++) {
                    mma_bf16(acc[m][n], ah[m], bh);
                    mma_bf16(acc[m][n], al[m], bh);
                    mma_bf16(acc[m][n], ah[m], bl);
                }
            }
        }

        #pragma unroll
        for (int m = 0; m < 2; m++) {
            const int r0 = t * B_TILE + mi * 32 + m * 16 + (lane >> 2);
            const int r1 = r0 + 8;
            const int s0 = srcp[r0], d0 = dstp[r0];
            const int s1 = srcp[r1], d1 = dstp[r1];
            #pragma unroll
            for (int n = 0; n < 5; n++) {
                const int j = ni * 40 + n * 8 + 2 * (lane & 3);
                const float2 u0 = *reinterpret_cast<const float2*>(g_UV + (size_t)s0 * 320 + j);
                const float2 v0 = *reinterpret_cast<const float2*>(g_UV + (size_t)d0 * 320 + 160 + j);
                const float2 u1 = *reinterpret_cast<const float2*>(g_UV + (size_t)s1 * 320 + j);
                const float2 v1 = *reinterpret_cast<const float2*>(g_UV + (size_t)d1 * 320 + 160 + j);
                const float b0 = s_bias[j], b1 = s_bias[j + 1];
                float2 o0, o1;
                o0.x = fmaxf(acc[m][n][0] + u0.x + v0.x + b0, 0.0f);
                o0.y = fmaxf(acc[m][n][1] + u0.y + v0.y + b1, 0.0f);
                o1.x = fmaxf(acc[m][n][2] + u1.x + v1.x + b0, 0.0f);
                o1.y = fmaxf(acc[m][n][3] + u1.y + v1.y + b1, 0.0f);
                *reinterpret_cast<float2*>(z_edge + (size_t)r0 * 160 + j) = o0;
                *reinterpret_cast<float2*>(z_edge + (size_t)r1 * 160 + j) = o1;
            }
        }
    }
}

// =====================================================================
// Kernel C: msg = sigmoid(P[dst]+Q[src]+bf) * softplus(R[dst]+S[src]+bs)
//           z_node[dst] += msg
// LUT entries pre-baked as (v0 - i*delta, delta): val = fma(tp, d, base)
// =====================================================================
static __device__ __forceinline__ float lut_eval(const float2* tab, float x) {
    float tp = fmaf(x, 512.0f / 20.0f, 256.0f);
    tp = fminf(fmaxf(tp, 0.0f), 511.5f);
    const float2 c = tab[(int)tp];
    return fmaf(tp, c.y, c.x);
}

__global__ __launch_bounds__(256)
void gate_assemble_kernel(const int* __restrict__ srcp,
                          const int* __restrict__ dstp,
                          const float* __restrict__ bf,
                          const float* __restrict__ bs,
                          float* __restrict__ z_node)
{
    __shared__ float2 t_sig[512];
    __shared__ float2 t_sp[512];
    __shared__ float s_bf[64], s_bs[64];

    const int tid = threadIdx.x;
    for (int i = tid; i < 512; i += 256) {
        const float x0 = -10.0f + (float)i * (20.0f / 512.0f);
        const float x1 = x0 + (20.0f / 512.0f);
        const float s0 = 1.0f / (1.0f + expf(-x0));
        const float s1 = 1.0f / (1.0f + expf(-x1));
        const float ds = s1 - s0;
        t_sig[i] = make_float2(s0 - (float)i * ds, ds);
        const float p0 = fmaxf(x0, 0.0f) + log1pf(expf(-fabsf(x0)));
        const float p1 = fmaxf(x1, 0.0f) + log1pf(expf(-fabsf(x1)));
        const float dp = p1 - p0;
        t_sp[i] = make_float2(p0 - (float)i * dp, dp);
    }
    if (tid < 64) { s_bf[tid] = bf[tid]; s_bs[tid] = bs[tid]; }
    __syncthreads();

    const int e = blockIdx.x * 64 + (tid >> 2);
    const int c0 = (tid & 3) * 16;
    const int d = dstp[e], s = srcp[e];
    const float4* Pf = reinterpret_cast<const float4*>(g_G1 + (size_t)d * 128 + c0);
    const float4* Qf = reinterpret_cast<const float4*>(g_G2 + (size_t)s * 128 + c0);
    const float4* Ps = reinterpret_cast<const float4*>(g_G1 + (size_t)d * 128 + 64 + c0);
    const float4* Qs = reinterpret_cast<const float4*>(g_G2 + (size_t)s * 128 + 64 + c0);
    float* out = z_node + (size_t)d * 64 + c0;

    #pragma unroll
    for (int j = 0; j < 4; j++) {
        const float4 pf = Pf[j], qf = Qf[j], ps = Ps[j], qs = Qs[j];
        const int c = c0 + 4 * j;
        float4 msg;
        {
            const float f = pf.x + qf.x + s_bf[c + 0];
            const float v = ps.x + qs.x + s_bs[c + 0];
            msg.x = lut_eval(t_sig, f) * fmaxf(lut_eval(t_sp, v), v);
        }
        {
            const float f = pf.y + qf.y + s_bf[c + 1];
            const float v = ps.y + qs.y + s_bs[c + 1];
            msg.y = lut_eval(t_sig, f) * fmaxf(lut_eval(t_sp, v), v);
        }
        {
            const float f = pf.z + qf.z + s_bf[c + 2];
            const float v = ps.z + qs.z + s_bs[c + 2];
            msg.z = lut_eval(t_sig, f) * fmaxf(lut_eval(t_sp, v), v);
        }
        {
            const float f = pf.w + qf.w + s_bf[c + 3];
            const float v = ps.w + qs.w + s_bs[c + 3];
            msg.w = lut_eval(t_sig, f) * fmaxf(lut_eval(t_sp, v), v);
        }
        atomicAdd(reinterpret_cast<float4*>(out + 4 * j), msg);
    }
}

extern "C" void kernel_launch(void* const* d_in, const int* in_sizes, int n_in,
                              void* d_out, int out_size)
{
    const float* z    = (const float*)d_in[0];
    const float* ea   = (const float*)d_in[1];
    const int*   eidx = (const int*)  d_in[2];
    const float* Wffw = (const float*)d_in[3];
    const float* bffw = (const float*)d_in[4];
    const float* Wf   = (const float*)d_in[5];
    const float* bf   = (const float*)d_in[6];
    const float* Ws   = (const float*)d_in[7];
    const float* bs   = (const float*)d_in[8];

    float* z_node = (float*)d_out;
    float* z_edge = (float*)d_out + (size_t)NNODE * 64;
    const int* srcp = eidx;
    const int* dstp = eidx + NE;

    // one-time infra (created on first, non-captured, correctness call)
    static cudaStream_t s2 = nullptr;
    static cudaEvent_t evA = nullptr, evC = nullptr;
    if (s2 == nullptr) {
        cudaStreamCreateWithFlags(&s2, cudaStreamNonBlocking);
        cudaEventCreateWithFlags(&evA, cudaEventDisableTiming);
        cudaEventCreateWithFlags(&evC, cudaEventDisableTiming);
        cudaFuncSetAttribute(node_gemm_kernel, cudaFuncAttributeMaxDynamicSharedMemorySize, A_SMEM);
        cudaFuncSetAttribute(edge_assemble_kernel, cudaFuncAttributeMaxDynamicSharedMemorySize, B_SMEM);
    }

    // stream 0: residual memcpy -> A -> fork
    cudaMemcpyAsync(z_node, z, (size_t)NNODE * 64 * sizeof(float),
                    cudaMemcpyDeviceToDevice, 0);
    node_gemm_kernel<<<148, A_THR, A_SMEM, 0>>>(z, Wffw, Wf, Ws);
    cudaEventRecord(evA, 0);

    // side stream: C (needs A's G1/G2 + memcpy'd z_node)
    cudaStreamWaitEvent(s2, evA, 0);
    gate_assemble_kernel<<<B_NT, 256, 0, s2>>>(srcp, dstp, bf, bs, z_node);
    cudaEventRecord(evC, s2);

    // stream 0: B (needs A's UV) runs concurrently with C
    edge_assemble_kernel<<<444, B_THR, B_SMEM, 0>>>(ea, srcp, dstp, Wffw, bffw, z_edge);

    // join
    cudaStreamWaitEvent(0, evC, 0);
}